// round 5
// baseline (speedup 1.0000x reference)
#include <cuda_runtime.h>
#include <cuda_bf16.h>
#include <math.h>

// ---------------- problem constants ----------------
#define NB 32768            // batch
#define NSF (2*NB)          // sample-frames
#define FEAT_K 592          // 578 padded to 16
#define COMB_K 136          // 132 padded to 8

typedef unsigned long long ull;

// ---------------- packed fp32x2 helpers (Blackwell FFMA2) ----------------
__device__ __forceinline__ ull pk_dup(float x) {
    ull r; unsigned u = __float_as_uint(x);
    asm("mov.b64 %0, {%1, %1};" : "=l"(r) : "r"(u));
    return r;
}
__device__ __forceinline__ void fma2(ull& d, ull a, ull b) {
    asm("fma.rn.f32x2 %0, %1, %2, %3;" : "=l"(d) : "l"(a), "l"(b), "l"(d));
}
__device__ __forceinline__ void unpk(ull v, float& lo, float& hi) {
    unsigned a, b;
    asm("mov.b64 {%0, %1}, %2;" : "=r"(a), "=r"(b) : "l"(v));
    lo = __uint_as_float(a); hi = __uint_as_float(b);
}

// ---------------- device scratch (static, no allocs) ----------------
__device__ float g_feats[(size_t)NSF * FEAT_K];   // ~155 MB
__device__ float g_emb[(size_t)NSF * 64];
__device__ int   g_dir[NSF];
__device__ float g_pos[NSF * 2];
__device__ float g_projwt[FEAT_K * 64];           // [k][e], zero-padded k>=578
__device__ float g_h1wt[COMB_K * 128];            // [k][o], zero-padded k>=132
__device__ float g_h2wt[128 * 128];               // [k][o]

// ---------------- kernel: weight transposes ----------------
__global__ void prep_kernel(const float* __restrict__ projw,
                            const float* __restrict__ h1w,
                            const float* __restrict__ h2w) {
    int i = blockIdx.x * 256 + threadIdx.x;
    const int N1 = FEAT_K * 64;
    const int N2 = COMB_K * 128;
    const int N3 = 128 * 128;
    if (i < N1) {
        int k = i / 64, e = i % 64;
        g_projwt[i] = (k < 578) ? projw[e * 578 + k] : 0.f;
    } else if (i < N1 + N2) {
        int j = i - N1;
        int k = j / 128, o = j % 128;
        g_h1wt[j] = (k < 132) ? h1w[o * 132 + k] : 0.f;
    } else if (i < N1 + N2 + N3) {
        int j = i - N1 - N2;
        int k = j / 128, o = j % 128;
        g_h2wt[j] = h2w[o * 128 + k];
    }
}

// ---------------- kernel: conv encoder (warp per sample-frame, packed f32x2) ----------------
// smem floats:
//  sw1[192] sb1[16] sw2p[2048](pairs) sb2p[32](pairs) sw3p[8192](pairs) sb3[64]  = 10544
//  per warp (7): xin[244] p1d[1152](dup) p2d[1024](dup) = 2420
#define ENC_WARPS 7
#define ENC_THREADS (ENC_WARPS * 32)
#define ENC_WEIGHTS 10544
#define ENC_PERWARP 2420
#define ENC_SMEM_FLOATS (ENC_WEIGHTS + ENC_WARPS * ENC_PERWARP)

__global__ void __launch_bounds__(ENC_THREADS, 2) encode_kernel(
    const int* __restrict__ frame, const int* __restrict__ ccol, const int* __restrict__ cobj,
    const float* __restrict__ w1g, const float* __restrict__ b1g,
    const float* __restrict__ w2g, const float* __restrict__ b2g,
    const float* __restrict__ w3g, const float* __restrict__ b3g)
{
    extern __shared__ float smem[];
    float* sw1  = smem;                 // [16][3][2][2]
    float* sb1  = sw1 + 192;
    float* sw2p = sb1 + 16;             // pairs: ((ic*4+t)*16+c)*2+sel  (sel: +0 ch c, +1 ch c+16)
    float* sb2p = sw2p + 2048;          // pairs: c*2+sel
    float* sw3p = sb2p + 32;            // pairs: ((ic*4+t)*32+l)*2+sel  (sel: +0 ch l, +1 ch l+32)
    float* sb3  = sw3p + 8192;
    float* swarp = sb3 + 64;

    int tid = threadIdx.x;
    for (int i = tid; i < 192; i += ENC_THREADS) sw1[i] = w1g[i];
    if (tid < 16) sb1[tid] = b1g[tid];
    for (int i = tid; i < 2048; i += ENC_THREADS) {
        int oc = i >> 6, rem = i & 63;
        int c = oc & 15, sel = oc >> 4;
        sw2p[(rem * 16 + c) * 2 + sel] = w2g[i];
    }
    if (tid < 32) sb2p[(tid & 15) * 2 + (tid >> 4)] = b2g[tid];
    for (int i = tid; i < 8192; i += ENC_THREADS) {
        int oc = i >> 7, rem = i & 127;
        int l = oc & 31, sel = oc >> 5;
        sw3p[(rem * 32 + l) * 2 + sel] = w3g[i];
    }
    if (tid < 64) sb3[tid] = b3g[tid];
    __syncthreads();

    int warp = tid >> 5, lane = tid & 31;
    int sf = blockIdx.x * ENC_WARPS + warp;
    if (sf >= NSF) return;

    float* wbase = swarp + warp * ENC_PERWARP;
    float* xin = wbase;                 // [3][9][9] padded (scalar)
    float* p1d = wbase + 244;           // [16][6][6] duplicated pairs
    float* p2d = wbase + 1396;          // [32][4][4] duplicated pairs
    float2* p1f2 = (float2*)p1d;
    float2* p2f2 = (float2*)p2d;
    const ull* p1du = (const ull*)p1d;
    const ull* p2du = (const ull*)p2d;
    const ull* w2u = (const ull*)sw2p;
    const ull* w3u = (const ull*)sw3p;

    const int* fb = frame + (size_t)sf * 147;

    // zero everything, then fill input interior (HWC -> CHW)
    for (int i = lane; i < ENC_PERWARP; i += 32) wbase[i] = 0.f;
    __syncwarp();
    for (int i = lane; i < 147; i += 32) {
        int y = i / 21, r = i % 21, x = r / 3, c = r % 3;
        xin[c * 81 + (y + 1) * 9 + (x + 1)] = (float)fb[i];
    }
    // dir/pos via ballot (first row-major position where ch0 == 10)
    {
        int v0 = fb[lane * 3];
        unsigned m0 = __ballot_sync(0xffffffffu, v0 == 10);
        int p2i = 32 + lane;
        int v1 = (p2i < 49) ? fb[p2i * 3] : 0;
        unsigned m1 = __ballot_sync(0xffffffffu, (p2i < 49) && (v1 == 10));
        if (lane == 0) {
            int idx = m0 ? (__ffs(m0) - 1) : (m1 ? (31 + __ffs(m1)) : -1);
            int d = 0; float py = 0.5f, px = 0.5f;
            if (idx >= 0) {
                d = fb[idx * 3 + 2] & 3;
                py = (float)(idx / 7) * (1.f / 6.f);
                px = (float)(idx % 7) * (1.f / 6.f);
            }
            g_dir[sf] = d;
            g_pos[sf * 2 + 0] = py;
            g_pos[sf * 2 + 1] = px;
        }
    }
    __syncwarp();

    // -------- conv1 (3->16, k2 pad1, out 8x8) + relu + pool2 -> p1d interior [16][4][4] dup
    {
        int c = lane & 15, half = lane >> 4;
        float w[12];
        #pragma unroll
        for (int j = 0; j < 12; j++) w[j] = sw1[c * 12 + j];
        float bias = sb1[c];
        #pragma unroll
        for (int t8 = 0; t8 < 8; t8++) {
            int pos = half * 8 + t8;
            int py = pos >> 2, px = pos & 3;
            float m = 0.f;
            #pragma unroll
            for (int dy = 0; dy < 2; dy++)
            #pragma unroll
            for (int dx = 0; dx < 2; dx++) {
                int oy = 2 * py + dy, ox = 2 * px + dx;
                float s = bias;
                #pragma unroll
                for (int ic = 0; ic < 3; ic++) {
                    const float* xp = xin + ic * 81 + oy * 9 + ox;
                    s += w[ic * 4 + 0] * xp[0] + w[ic * 4 + 1] * xp[1]
                       + w[ic * 4 + 2] * xp[9] + w[ic * 4 + 3] * xp[10];
                }
                m = fmaxf(m, s);
            }
            p1f2[c * 36 + (py + 1) * 6 + (px + 1)] = make_float2(m, m);
        }
    }
    __syncwarp();

    // -------- conv2 (16->32) + relu + pool -> p2d interior [32][2][2] dup
    // lane = (c in 0..15, h in 0..1); channel pair (c, c+16), conv-output rows {2h, 2h+1}
    {
        int c = lane & 15, h = lane >> 4;
        ull acc[8];
        #pragma unroll
        for (int i = 0; i < 8; i++) acc[i] = 0ULL;
        #pragma unroll 4
        for (int ic = 0; ic < 16; ic++) {
            ull in[3][5];
            #pragma unroll
            for (int r = 0; r < 3; r++)
                #pragma unroll
                for (int x = 0; x < 5; x++)
                    in[r][x] = p1du[ic * 36 + (2 * h + r) * 6 + x];
            ull wa = w2u[(ic * 4 + 0) * 16 + c];
            ull wb = w2u[(ic * 4 + 1) * 16 + c];
            ull wc = w2u[(ic * 4 + 2) * 16 + c];
            ull wd = w2u[(ic * 4 + 3) * 16 + c];
            #pragma unroll
            for (int ry = 0; ry < 2; ry++)
                #pragma unroll
                for (int ox = 0; ox < 4; ox++) {
                    ull* a = &acc[ry * 4 + ox];
                    fma2(*a, wa, in[ry][ox]);
                    fma2(*a, wb, in[ry][ox + 1]);
                    fma2(*a, wc, in[ry + 1][ox]);
                    fma2(*a, wd, in[ry + 1][ox + 1]);
                }
        }
        ull bp = ((const ull*)sb2p)[c];
        float blo, bhi; unpk(bp, blo, bhi);
        #pragma unroll
        for (int px = 0; px < 2; px++) {
            float l0, h0, l1, h1, l2, h2, l3, h3;
            unpk(acc[0 * 4 + 2 * px],     l0, h0);
            unpk(acc[0 * 4 + 2 * px + 1], l1, h1);
            unpk(acc[1 * 4 + 2 * px],     l2, h2);
            unpk(acc[1 * 4 + 2 * px + 1], l3, h3);
            float mlo = fmaxf(fmaxf(l0, l1), fmaxf(l2, l3));
            float mhi = fmaxf(fmaxf(h0, h1), fmaxf(h2, h3));
            float vlo = fmaxf(mlo + blo, 0.f);
            float vhi = fmaxf(mhi + bhi, 0.f);
            p2f2[c * 16 + (h + 1) * 4 + (px + 1)]        = make_float2(vlo, vlo);
            p2f2[(c + 16) * 16 + (h + 1) * 4 + (px + 1)] = make_float2(vhi, vhi);
        }
    }
    __syncwarp();

    // -------- conv3 (32->64, out 3x3) + relu -> feats; lane owns channel pair (lane, lane+32)
    {
        ull a[9];
        #pragma unroll
        for (int i = 0; i < 9; i++) a[i] = 0ULL;
        #pragma unroll 4
        for (int ic = 0; ic < 32; ic++) {
            ull in[16];
            #pragma unroll
            for (int i = 0; i < 16; i++) in[i] = p2du[ic * 16 + i];
            ull w0 = w3u[(ic * 4 + 0) * 32 + lane];
            ull w1 = w3u[(ic * 4 + 1) * 32 + lane];
            ull w2 = w3u[(ic * 4 + 2) * 32 + lane];
            ull w3 = w3u[(ic * 4 + 3) * 32 + lane];
            #pragma unroll
            for (int oy = 0; oy < 3; oy++)
                #pragma unroll
                for (int ox = 0; ox < 3; ox++) {
                    ull* ac = &a[oy * 3 + ox];
                    fma2(*ac, w0, in[oy * 4 + ox]);
                    fma2(*ac, w1, in[oy * 4 + ox + 1]);
                    fma2(*ac, w2, in[(oy + 1) * 4 + ox]);
                    fma2(*ac, w3, in[(oy + 1) * 4 + ox + 1]);
                }
        }
        float* fbase = g_feats + (size_t)sf * FEAT_K;
        float b0 = sb3[lane], b1v = sb3[lane + 32];
        #pragma unroll
        for (int p = 0; p < 9; p++) {
            float lo, hi; unpk(a[p], lo, hi);
            fbase[lane * 9 + p]        = fmaxf(lo + b0, 0.f);
            fbase[(lane + 32) * 9 + p] = fmaxf(hi + b1v, 0.f);
        }
        if (lane == 0) {
            fbase[576] = (float)ccol[sf];
            fbase[577] = (float)cobj[sf];
        }
        if (lane < 14) fbase[578 + lane] = 0.f;
    }
}

// ---------------- kernel: proj GEMM  emb[2B,64] = relu(feats * Wt + b), packed ----------------
__global__ void __launch_bounds__(256) proj_kernel(const float* __restrict__ projb)
{
    __shared__ float As[16][68];       // [k][m]
    __shared__ ull   Bsu[16 * 32];     // [k][n pairs]
    int tid = threadIdx.x;
    int m0 = blockIdx.x * 64;
    int tx = tid & 15, ty = tid >> 4;
    ull acc[4][2];
    #pragma unroll
    for (int i = 0; i < 4; i++) { acc[i][0] = 0ULL; acc[i][1] = 0ULL; }

    for (int k0 = 0; k0 < FEAT_K; k0 += 16) {
        {
            int m = tid >> 2, kq = (tid & 3) * 4;
            float4 av = *reinterpret_cast<const float4*>(g_feats + (size_t)(m0 + m) * FEAT_K + k0 + kq);
            As[kq + 0][m] = av.x; As[kq + 1][m] = av.y; As[kq + 2][m] = av.z; As[kq + 3][m] = av.w;
        }
        {
            int k = tid >> 4, nq = (tid & 15) * 4;
            float4 bv = *reinterpret_cast<const float4*>(g_projwt + (k0 + k) * 64 + nq);
            float2* bf2 = (float2*)Bsu;
            bf2[k * 32 + (tid & 15) * 2 + 0] = make_float2(bv.x, bv.y);
            bf2[k * 32 + (tid & 15) * 2 + 1] = make_float2(bv.z, bv.w);
        }
        __syncthreads();
        #pragma unroll
        for (int k = 0; k < 16; k++) {
            ull b0 = Bsu[k * 32 + tx * 2], b1 = Bsu[k * 32 + tx * 2 + 1];
            #pragma unroll
            for (int i = 0; i < 4; i++) {
                ull ad = pk_dup(As[k][ty * 4 + i]);
                fma2(acc[i][0], ad, b0);
                fma2(acc[i][1], ad, b1);
            }
        }
        __syncthreads();
    }
    #pragma unroll
    for (int i = 0; i < 4; i++) {
        int m = m0 + ty * 4 + i;
        #pragma unroll
        for (int j2 = 0; j2 < 2; j2++) {
            int n = tx * 4 + j2 * 2;
            float lo, hi; unpk(acc[i][j2], lo, hi);
            g_emb[(size_t)m * 64 + n]     = fmaxf(lo + projb[n], 0.f);
            g_emb[(size_t)m * 64 + n + 1] = fmaxf(hi + projb[n + 1], 0.f);
        }
    }
}

// ---------------- kernel: fused comb + MLP (h1 -> LN -> relu -> h2 -> relu -> h3), packed ----------------
// dynamic smem floats: As[136*129] + Bs[136*128] + Hs[128*129] + sh3t[128*8]
#define MLP_AS (136 * 129)
#define MLP_BS (136 * 128)
#define MLP_HS (128 * 129)
#define MLP_SH3 (128 * 8)
#define MLP_SMEM_FLOATS (MLP_AS + MLP_BS + MLP_HS + MLP_SH3)

__global__ void __launch_bounds__(256) mlp_kernel(
    const float* __restrict__ h1b, const float* __restrict__ lng, const float* __restrict__ lnb,
    const float* __restrict__ h2b, const float* __restrict__ h3w, const float* __restrict__ h3b,
    float* __restrict__ out)
{
    extern __shared__ float smem[];
    float* As   = smem;                 // comb^T [k][m] stride 129; later h2^T
    float* Bsf  = As + MLP_AS;          // weights [k][n] (float view)
    float* Hs   = Bsf + MLP_BS;         // h^T [feature][m] stride 129
    float* sh3f = Hs + MLP_HS;          // h3 transposed [k][8] (j<7 real)
    ull* Bsu  = (ull*)Bsf;
    ull* sh3u = (ull*)sh3f;

    int tid = threadIdx.x;
    int m0 = blockIdx.x * 128;

    // ---- build comb directly into As (fused, no global comb buffer)
    for (int i = tid; i < 128 * COMB_K; i += 256) {
        int m = i / COMB_K, k = i - m * COMB_K;
        int b = m0 + m;
        float v;
        if (k < 64)       v = g_emb[(size_t)b * 64 + k];
        else if (k < 128) v = g_emb[(size_t)(NB + b) * 64 + (k - 64)];
        else if (k < 130) {
            int delta = ((g_dir[NB + b] - g_dir[b]) + 4) & 3;
            float ang = (float)delta * (2.0f * 3.14159f / 4.0f);
            v = (k == 128) ? sinf(ang) : cosf(ang);
        }
        else if (k == 130) v = g_pos[(NB + b) * 2 + 0] - g_pos[b * 2 + 0];
        else if (k == 131) v = g_pos[(NB + b) * 2 + 1] - g_pos[b * 2 + 1];
        else v = 0.f;
        As[k * 129 + m] = v;
    }
    for (int i = tid; i < (COMB_K * 128) / 4; i += 256)
        ((float4*)Bsf)[i] = ((const float4*)g_h1wt)[i];
    for (int i = tid; i < 128 * 8; i += 256) {
        int k = i >> 3, j = i & 7;
        sh3f[i] = (j < 7) ? h3w[j * 128 + k] : 0.f;
    }
    __syncthreads();

    int tx = tid & 15, ty = tid >> 4;

    // ---- GEMM1: h[128m][128n] = comb * h1wt  (packed n-pairs)
    {
        ull acc[8][4];
        #pragma unroll
        for (int i = 0; i < 8; i++)
            #pragma unroll
            for (int j = 0; j < 4; j++) acc[i][j] = 0ULL;
        for (int k = 0; k < COMB_K; k++) {
            ull bp[4];
            #pragma unroll
            for (int j = 0; j < 4; j++) bp[j] = Bsu[k * 64 + tx * 4 + j];
            #pragma unroll
            for (int i = 0; i < 8; i++) {
                ull ad = pk_dup(As[k * 129 + ty * 8 + i]);
                #pragma unroll
                for (int j = 0; j < 4; j++) fma2(acc[i][j], ad, bp[j]);
            }
        }
        // write pre-LN h (+bias) transposed into Hs[feature][m]
        #pragma unroll
        for (int j = 0; j < 4; j++) {
            int n = tx * 8 + j * 2;
            float bn0 = h1b[n], bn1 = h1b[n + 1];
            #pragma unroll
            for (int i = 0; i < 8; i++) {
                int m = ty * 8 + i;
                float lo, hi; unpk(acc[i][j], lo, hi);
                Hs[n * 129 + m]       = lo + bn0;
                Hs[(n + 1) * 129 + m] = hi + bn1;
            }
        }
    }
    __syncthreads();

    // load h2 weights (Bs free now)
    for (int i = tid; i < (128 * 128) / 4; i += 256)
        ((float4*)Bsf)[i] = ((const float4*)g_h2wt)[i];
    // LayerNorm + relu: 2 threads per sample row
    {
        int m = tid >> 1, half = tid & 1;
        int kb = half * 64;
        float s = 0.f, s2 = 0.f;
        for (int k = kb; k < kb + 64; k++) {
            float v = Hs[k * 129 + m];
            s += v; s2 += v * v;
        }
        s  += __shfl_xor_sync(0xffffffffu, s, 1);
        s2 += __shfl_xor_sync(0xffffffffu, s2, 1);
        float mu = s * (1.f / 128.f);
        float var = s2 * (1.f / 128.f) - mu * mu;
        float rs = rsqrtf(var + 1e-5f);
        for (int k = kb; k < kb + 64; k++) {
            float v = Hs[k * 129 + m];
            Hs[k * 129 + m] = fmaxf((v - mu) * rs * lng[k] + lnb[k], 0.f);
        }
    }
    __syncthreads();

    // ---- GEMM2: h2 = relu(h * h2wt + b)  (packed)
    {
        ull acc[8][4];
        #pragma unroll
        for (int i = 0; i < 8; i++)
            #pragma unroll
            for (int j = 0; j < 4; j++) acc[i][j] = 0ULL;
        for (int k = 0; k < 128; k++) {
            ull bp[4];
            #pragma unroll
            for (int j = 0; j < 4; j++) bp[j] = Bsu[k * 64 + tx * 4 + j];
            #pragma unroll
            for (int i = 0; i < 8; i++) {
                ull ad = pk_dup(Hs[k * 129 + ty * 8 + i]);
                #pragma unroll
                for (int j = 0; j < 4; j++) fma2(acc[i][j], ad, bp[j]);
            }
        }
        __syncthreads();   // done reading As (comb) — reuse as h2^T
        #pragma unroll
        for (int j = 0; j < 4; j++) {
            int n = tx * 8 + j * 2;
            float bn0 = h2b[n], bn1 = h2b[n + 1];
            #pragma unroll
            for (int i = 0; i < 8; i++) {
                int m = ty * 8 + i;
                float lo, hi; unpk(acc[i][j], lo, hi);
                As[n * 129 + m]       = fmaxf(lo + bn0, 0.f);
                As[(n + 1) * 129 + m] = fmaxf(hi + bn1, 0.f);
            }
        }
    }
    __syncthreads();

    // ---- h3: out[m][7]  (packed j-pairs via transposed sh3)
    if (tid < 128) {
        int m = tid;
        ull acc[4];
        #pragma unroll
        for (int j = 0; j < 4; j++) acc[j] = 0ULL;
        for (int k = 0; k < 128; k++) {
            ull ad = pk_dup(As[k * 129 + m]);
            #pragma unroll
            for (int j = 0; j < 4; j++) fma2(acc[j], ad, sh3u[k * 4 + j]);
        }
        float r[8];
        #pragma unroll
        for (int j = 0; j < 4; j++) unpk(acc[j], r[2 * j], r[2 * j + 1]);
        #pragma unroll
        for (int j = 0; j < 7; j++)
            out[(size_t)(m0 + m) * 7 + j] = r[j] + h3b[j];
    }
}

// ---------------- launch ----------------
extern "C" void kernel_launch(void* const* d_in, const int* in_sizes, int n_in,
                              void* d_out, int out_size)
{
    const int*   frame = (const int*)d_in[0];
    const int*   ccol  = (const int*)d_in[1];
    const int*   cobj  = (const int*)d_in[2];
    const float* c1w = (const float*)d_in[3];
    const float* c1b = (const float*)d_in[4];
    const float* c2w = (const float*)d_in[5];
    const float* c2b = (const float*)d_in[6];
    const float* c3w = (const float*)d_in[7];
    const float* c3b = (const float*)d_in[8];
    const float* pw  = (const float*)d_in[9];
    const float* pb  = (const float*)d_in[10];
    const float* h1w = (const float*)d_in[11];
    const float* h1b = (const float*)d_in[12];
    const float* lng = (const float*)d_in[13];
    const float* lnb = (const float*)d_in[14];
    const float* h2w = (const float*)d_in[15];
    const float* h2b = (const float*)d_in[16];
    const float* h3w = (const float*)d_in[17];
    const float* h3b = (const float*)d_in[18];
    float* out = (float*)d_out;

    cudaFuncSetAttribute(encode_kernel, cudaFuncAttributeMaxDynamicSharedMemorySize,
                         ENC_SMEM_FLOATS * (int)sizeof(float));
    cudaFuncSetAttribute(mlp_kernel, cudaFuncAttributeMaxDynamicSharedMemorySize,
                         MLP_SMEM_FLOATS * (int)sizeof(float));

    {
        int total = FEAT_K * 64 + COMB_K * 128 + 128 * 128;
        prep_kernel<<<(total + 255) / 256, 256>>>(pw, h1w, h2w);
    }
    encode_kernel<<<(NSF + ENC_WARPS - 1) / ENC_WARPS, ENC_THREADS,
                    ENC_SMEM_FLOATS * sizeof(float)>>>(
        frame, ccol, cobj, c1w, c1b, c2w, c2b, c3w, c3b);
    proj_kernel<<<NSF / 64, 256>>>(pb);
    mlp_kernel<<<NB / 128, 256, MLP_SMEM_FLOATS * sizeof(float)>>>(
        h1b, lng, lnb, h2b, h3w, h3b, out);
}

// round 8
// speedup vs baseline: 1.2655x; 1.2655x over previous
#include <cuda_runtime.h>
#include <cuda_bf16.h>
#include <math.h>

// ---------------- problem constants ----------------
#define NB 32768            // batch
#define NSF (2*NB)          // sample-frames
#define FEAT_K 592          // 578 padded to 16
#define COMB_K 136          // 132 padded to 8

typedef unsigned long long ull;

// ---------------- packed fp32x2 helpers (Blackwell FFMA2) ----------------
__device__ __forceinline__ ull pk_dup(float x) {
    ull r; unsigned u = __float_as_uint(x);
    asm("mov.b64 %0, {%1, %1};" : "=l"(r) : "r"(u));
    return r;
}
__device__ __forceinline__ void fma2(ull& d, ull a, ull b) {
    asm("fma.rn.f32x2 %0, %1, %2, %3;" : "=l"(d) : "l"(a), "l"(b), "l"(d));
}
__device__ __forceinline__ void unpk(ull v, float& lo, float& hi) {
    unsigned a, b;
    asm("mov.b64 {%0, %1}, %2;" : "=r"(a), "=r"(b) : "l"(v));
    lo = __uint_as_float(a); hi = __uint_as_float(b);
}

// ---------------- device scratch (static, no allocs) ----------------
__device__ float g_feats[(size_t)NSF * FEAT_K];   // ~155 MB
__device__ float g_emb[(size_t)NSF * 64];
__device__ int   g_dir[NSF];
__device__ float g_pos[NSF * 2];
__device__ float g_projwt[FEAT_K * 64];           // [k][e], zero-padded k>=578
__device__ float g_h1wt[COMB_K * 128];            // [k][o], zero-padded k>=132
__device__ float g_h2wt[128 * 128];               // [k][o]

// ---------------- kernel: weight transposes ----------------
__global__ void prep_kernel(const float* __restrict__ projw,
                            const float* __restrict__ h1w,
                            const float* __restrict__ h2w) {
    int i = blockIdx.x * 256 + threadIdx.x;
    const int N1 = FEAT_K * 64;
    const int N2 = COMB_K * 128;
    const int N3 = 128 * 128;
    if (i < N1) {
        int k = i / 64, e = i % 64;
        g_projwt[i] = (k < 578) ? projw[e * 578 + k] : 0.f;
    } else if (i < N1 + N2) {
        int j = i - N1;
        int k = j / 128, o = j % 128;
        g_h1wt[j] = (k < 132) ? h1w[o * 132 + k] : 0.f;
    } else if (i < N1 + N2 + N3) {
        int j = i - N1 - N2;
        int k = j / 128, o = j % 128;
        g_h2wt[j] = h2w[o * 128 + k];
    }
}

// ---------------- kernel: conv encoder (warp per sample-frame, packed f32x2) ----------------
// smem floats:
//  sw1[192] sb1[16] sw2p[2048](pairs) sb2p[32](pairs) sw3p[8192](pairs) sb3[64]  = 10544
//  per warp (8): xin[244] p1d[1152](dup) p2d[256](dup, real 2x2 only) = 1652
#define ENC_WARPS 8
#define ENC_THREADS (ENC_WARPS * 32)
#define ENC_WEIGHTS 10544
#define ENC_PERWARP 1652
#define ENC_SMEM_FLOATS (ENC_WEIGHTS + ENC_WARPS * ENC_PERWARP)

__global__ void __launch_bounds__(ENC_THREADS, 2) encode_kernel(
    const int* __restrict__ frame, const int* __restrict__ ccol, const int* __restrict__ cobj,
    const float* __restrict__ w1g, const float* __restrict__ b1g,
    const float* __restrict__ w2g, const float* __restrict__ b2g,
    const float* __restrict__ w3g, const float* __restrict__ b3g)
{
    extern __shared__ float smem[];
    float* sw1  = smem;                 // [16][3][2][2]
    float* sb1  = sw1 + 192;
    float* sw2p = sb1 + 16;             // pairs: ((ic*4+t)*16+c)*2+sel  (sel: +0 ch c, +1 ch c+16)
    float* sb2p = sw2p + 2048;          // pairs: c*2+sel
    float* sw3p = sb2p + 32;            // pairs: ((ic*4+t)*32+l)*2+sel  (sel: +0 ch l, +1 ch l+32)
    float* sb3  = sw3p + 8192;
    float* swarp = sb3 + 64;

    int tid = threadIdx.x;
    for (int i = tid; i < 192; i += ENC_THREADS) sw1[i] = w1g[i];
    if (tid < 16) sb1[tid] = b1g[tid];
    for (int i = tid; i < 2048; i += ENC_THREADS) {
        int oc = i >> 6, rem = i & 63;
        int c = oc & 15, sel = oc >> 4;
        sw2p[(rem * 16 + c) * 2 + sel] = w2g[i];
    }
    if (tid < 32) sb2p[(tid & 15) * 2 + (tid >> 4)] = b2g[tid];
    for (int i = tid; i < 8192; i += ENC_THREADS) {
        int oc = i >> 7, rem = i & 127;
        int l = oc & 31, sel = oc >> 5;
        sw3p[(rem * 32 + l) * 2 + sel] = w3g[i];
    }
    if (tid < 64) sb3[tid] = b3g[tid];
    __syncthreads();

    int warp = tid >> 5, lane = tid & 31;
    int sf = blockIdx.x * ENC_WARPS + warp;
    if (sf >= NSF) return;

    float* wbase = swarp + warp * ENC_PERWARP;
    float* xin = wbase;                 // [3][9][9] padded (scalar)
    float* p1d = wbase + 244;           // [16][6][6] duplicated pairs
    float* p2d = wbase + 1396;          // [32][2][2] duplicated pairs (real only)
    float2* p1f2 = (float2*)p1d;
    float2* p2f2 = (float2*)p2d;
    const ull* p1du = (const ull*)p1d;
    const ull* p2du = (const ull*)p2d;
    const ull* w2u = (const ull*)sw2p;
    const ull* w3u = (const ull*)sw3p;

    const int* fb = frame + (size_t)sf * 147;

    // zero xin + p1d (p2d is fully written by conv2), then fill input interior (HWC -> CHW)
    for (int i = lane; i < 1396; i += 32) wbase[i] = 0.f;
    __syncwarp();
    for (int i = lane; i < 147; i += 32) {
        int y = i / 21, r = i % 21, x = r / 3, c = r % 3;
        xin[c * 81 + (y + 1) * 9 + (x + 1)] = (float)fb[i];
    }
    // dir/pos via ballot (first row-major position where ch0 == 10)
    {
        int v0 = fb[lane * 3];
        unsigned m0 = __ballot_sync(0xffffffffu, v0 == 10);
        int p2i = 32 + lane;
        int v1 = (p2i < 49) ? fb[p2i * 3] : 0;
        unsigned m1 = __ballot_sync(0xffffffffu, (p2i < 49) && (v1 == 10));
        if (lane == 0) {
            int idx = m0 ? (__ffs(m0) - 1) : (m1 ? (31 + __ffs(m1)) : -1);
            int d = 0; float py = 0.5f, px = 0.5f;
            if (idx >= 0) {
                d = fb[idx * 3 + 2] & 3;
                py = (float)(idx / 7) * (1.f / 6.f);
                px = (float)(idx % 7) * (1.f / 6.f);
            }
            g_dir[sf] = d;
            g_pos[sf * 2 + 0] = py;
            g_pos[sf * 2 + 1] = px;
        }
    }
    __syncwarp();

    // -------- conv1 (3->16, k2 pad1, out 8x8) + relu + pool2 -> p1d interior [16][4][4] dup
    {
        int c = lane & 15, half = lane >> 4;
        float w[12];
        #pragma unroll
        for (int j = 0; j < 12; j++) w[j] = sw1[c * 12 + j];
        float bias = sb1[c];
        #pragma unroll
        for (int t8 = 0; t8 < 8; t8++) {
            int pos = half * 8 + t8;
            int py = pos >> 2, px = pos & 3;
            float m = 0.f;
            #pragma unroll
            for (int dy = 0; dy < 2; dy++)
            #pragma unroll
            for (int dx = 0; dx < 2; dx++) {
                int oy = 2 * py + dy, ox = 2 * px + dx;
                float s = bias;
                #pragma unroll
                for (int ic = 0; ic < 3; ic++) {
                    const float* xp = xin + ic * 81 + oy * 9 + ox;
                    s += w[ic * 4 + 0] * xp[0] + w[ic * 4 + 1] * xp[1]
                       + w[ic * 4 + 2] * xp[9] + w[ic * 4 + 3] * xp[10];
                }
                m = fmaxf(m, s);
            }
            p1f2[c * 36 + (py + 1) * 6 + (px + 1)] = make_float2(m, m);
        }
    }
    __syncwarp();

    // -------- conv2 (16->32) + relu + pool -> p2d [32][2][2] dup (real only)
    // lane = (c in 0..15, h in 0..1); channel pair (c, c+16), conv-output rows {2h, 2h+1}
    {
        int c = lane & 15, h = lane >> 4;
        ull acc[8];
        #pragma unroll
        for (int i = 0; i < 8; i++) acc[i] = 0ULL;
        #pragma unroll 4
        for (int ic = 0; ic < 16; ic++) {
            ull in[3][5];
            #pragma unroll
            for (int r = 0; r < 3; r++)
                #pragma unroll
                for (int x = 0; x < 5; x++)
                    in[r][x] = p1du[ic * 36 + (2 * h + r) * 6 + x];
            ull wa = w2u[(ic * 4 + 0) * 16 + c];
            ull wb = w2u[(ic * 4 + 1) * 16 + c];
            ull wc = w2u[(ic * 4 + 2) * 16 + c];
            ull wd = w2u[(ic * 4 + 3) * 16 + c];
            #pragma unroll
            for (int ry = 0; ry < 2; ry++)
                #pragma unroll
                for (int ox = 0; ox < 4; ox++) {
                    ull* a = &acc[ry * 4 + ox];
                    fma2(*a, wa, in[ry][ox]);
                    fma2(*a, wb, in[ry][ox + 1]);
                    fma2(*a, wc, in[ry + 1][ox]);
                    fma2(*a, wd, in[ry + 1][ox + 1]);
                }
        }
        ull bp = ((const ull*)sb2p)[c];
        float blo, bhi; unpk(bp, blo, bhi);
        #pragma unroll
        for (int px = 0; px < 2; px++) {
            float l0, h0, l1, h1, l2, h2, l3, h3;
            unpk(acc[0 * 4 + 2 * px],     l0, h0);
            unpk(acc[0 * 4 + 2 * px + 1], l1, h1);
            unpk(acc[1 * 4 + 2 * px],     l2, h2);
            unpk(acc[1 * 4 + 2 * px + 1], l3, h3);
            float mlo = fmaxf(fmaxf(l0, l1), fmaxf(l2, l3));
            float mhi = fmaxf(fmaxf(h0, h1), fmaxf(h2, h3));
            float vlo = fmaxf(mlo + blo, 0.f);
            float vhi = fmaxf(mhi + bhi, 0.f);
            // pooled output position (h, px) — store real 2x2 only
            p2f2[c * 4 + h * 2 + px]        = make_float2(vlo, vlo);
            p2f2[(c + 16) * 4 + h * 2 + px] = make_float2(vhi, vhi);
        }
    }
    __syncwarp();

    // -------- conv3 (32->64, out 3x3) + relu -> feats; SCATTER from 4 real pixels.
    // pixel (iy,ix) contributes to out[iy+?][ix+?]:
    //   out[iy  ][ix  ] += w[1][1]*v ; out[iy  ][ix+1] += w[1][0]*v
    //   out[iy+1][ix  ] += w[0][1]*v ; out[iy+1][ix+1] += w[0][0]*v
    // lane owns channel pair (lane, lane+32)
    {
        ull a[9];
        #pragma unroll
        for (int i = 0; i < 9; i++) a[i] = 0ULL;
        #pragma unroll 4
        for (int ic = 0; ic < 32; ic++) {
            ull v00 = p2du[ic * 4 + 0];
            ull v01 = p2du[ic * 4 + 1];
            ull v10 = p2du[ic * 4 + 2];
            ull v11 = p2du[ic * 4 + 3];
            ull w00 = w3u[(ic * 4 + 0) * 32 + lane];   // w[0][0]
            ull w01 = w3u[(ic * 4 + 1) * 32 + lane];   // w[0][1]
            ull w10 = w3u[(ic * 4 + 2) * 32 + lane];   // w[1][0]
            ull w11 = w3u[(ic * 4 + 3) * 32 + lane];   // w[1][1]
            // pixel (0,0) -> outs (0,0)(0,1)(1,0)(1,1)
            fma2(a[0], w11, v00); fma2(a[1], w10, v00);
            fma2(a[3], w01, v00); fma2(a[4], w00, v00);
            // pixel (0,1) -> outs (0,1)(0,2)(1,1)(1,2)
            fma2(a[1], w11, v01); fma2(a[2], w10, v01);
            fma2(a[4], w01, v01); fma2(a[5], w00, v01);
            // pixel (1,0) -> outs (1,0)(1,1)(2,0)(2,1)
            fma2(a[3], w11, v10); fma2(a[4], w10, v10);
            fma2(a[6], w01, v10); fma2(a[7], w00, v10);
            // pixel (1,1) -> outs (1,1)(1,2)(2,1)(2,2)
            fma2(a[4], w11, v11); fma2(a[5], w10, v11);
            fma2(a[7], w01, v11); fma2(a[8], w00, v11);
        }
        float* fbase = g_feats + (size_t)sf * FEAT_K;
        float b0 = sb3[lane], b1v = sb3[lane + 32];
        #pragma unroll
        for (int p = 0; p < 9; p++) {
            float lo, hi; unpk(a[p], lo, hi);
            fbase[lane * 9 + p]        = fmaxf(lo + b0, 0.f);
            fbase[(lane + 32) * 9 + p] = fmaxf(hi + b1v, 0.f);
        }
        if (lane == 0) {
            fbase[576] = (float)ccol[sf];
            fbase[577] = (float)cobj[sf];
        }
        if (lane < 14) fbase[578 + lane] = 0.f;
    }
}

// ---------------- kernel: proj GEMM  emb[2B,64] = relu(feats * Wt + b), packed ----------------
__global__ void __launch_bounds__(256) proj_kernel(const float* __restrict__ projb)
{
    __shared__ float As[16][68];       // [k][m]
    __shared__ ull   Bsu[16 * 32];     // [k][n pairs]
    int tid = threadIdx.x;
    int m0 = blockIdx.x * 64;
    int tx = tid & 15, ty = tid >> 4;
    ull acc[4][2];
    #pragma unroll
    for (int i = 0; i < 4; i++) { acc[i][0] = 0ULL; acc[i][1] = 0ULL; }

    for (int k0 = 0; k0 < FEAT_K; k0 += 16) {
        {
            int m = tid >> 2, kq = (tid & 3) * 4;
            float4 av = *reinterpret_cast<const float4*>(g_feats + (size_t)(m0 + m) * FEAT_K + k0 + kq);
            As[kq + 0][m] = av.x; As[kq + 1][m] = av.y; As[kq + 2][m] = av.z; As[kq + 3][m] = av.w;
        }
        {
            int k = tid >> 4, nq = (tid & 15) * 4;
            float4 bv = *reinterpret_cast<const float4*>(g_projwt + (k0 + k) * 64 + nq);
            float2* bf2 = (float2*)Bsu;
            bf2[k * 32 + (tid & 15) * 2 + 0] = make_float2(bv.x, bv.y);
            bf2[k * 32 + (tid & 15) * 2 + 1] = make_float2(bv.z, bv.w);
        }
        __syncthreads();
        #pragma unroll
        for (int k = 0; k < 16; k++) {
            ull b0 = Bsu[k * 32 + tx * 2], b1 = Bsu[k * 32 + tx * 2 + 1];
            #pragma unroll
            for (int i = 0; i < 4; i++) {
                ull ad = pk_dup(As[k][ty * 4 + i]);
                fma2(acc[i][0], ad, b0);
                fma2(acc[i][1], ad, b1);
            }
        }
        __syncthreads();
    }
    #pragma unroll
    for (int i = 0; i < 4; i++) {
        int m = m0 + ty * 4 + i;
        #pragma unroll
        for (int j2 = 0; j2 < 2; j2++) {
            int n = tx * 4 + j2 * 2;
            float lo, hi; unpk(acc[i][j2], lo, hi);
            g_emb[(size_t)m * 64 + n]     = fmaxf(lo + projb[n], 0.f);
            g_emb[(size_t)m * 64 + n + 1] = fmaxf(hi + projb[n + 1], 0.f);
        }
    }
}

// ---------------- kernel: fused comb + MLP (h1 -> LN -> relu -> h2 -> relu -> h3), packed ----------------
// dynamic smem floats: As[136*129] + Bs[136*128] + Hs[128*129] + sh3t[128*8]
#define MLP_AS (136 * 129)
#define MLP_BS (136 * 128)
#define MLP_HS (128 * 129)
#define MLP_SH3 (128 * 8)
#define MLP_SMEM_FLOATS (MLP_AS + MLP_BS + MLP_HS + MLP_SH3)

__global__ void __launch_bounds__(256) mlp_kernel(
    const float* __restrict__ h1b, const float* __restrict__ lng, const float* __restrict__ lnb,
    const float* __restrict__ h2b, const float* __restrict__ h3w, const float* __restrict__ h3b,
    float* __restrict__ out)
{
    extern __shared__ float smem[];
    float* As   = smem;                 // comb^T [k][m] stride 129; later h2^T
    float* Bsf  = As + MLP_AS;          // weights [k][n] (float view)
    float* Hs   = Bsf + MLP_BS;         // h^T [feature][m] stride 129
    float* sh3f = Hs + MLP_HS;          // h3 transposed [k][8] (j<7 real)
    ull* Bsu  = (ull*)Bsf;
    ull* sh3u = (ull*)sh3f;

    int tid = threadIdx.x;
    int m0 = blockIdx.x * 128;

    // ---- build comb directly into As (fused, no global comb buffer)
    for (int i = tid; i < 128 * COMB_K; i += 256) {
        int m = i / COMB_K, k = i - m * COMB_K;
        int b = m0 + m;
        float v;
        if (k < 64)       v = g_emb[(size_t)b * 64 + k];
        else if (k < 128) v = g_emb[(size_t)(NB + b) * 64 + (k - 64)];
        else if (k < 130) {
            int delta = ((g_dir[NB + b] - g_dir[b]) + 4) & 3;
            float ang = (float)delta * (2.0f * 3.14159f / 4.0f);
            v = (k == 128) ? sinf(ang) : cosf(ang);
        }
        else if (k == 130) v = g_pos[(NB + b) * 2 + 0] - g_pos[b * 2 + 0];
        else if (k == 131) v = g_pos[(NB + b) * 2 + 1] - g_pos[b * 2 + 1];
        else v = 0.f;
        As[k * 129 + m] = v;
    }
    for (int i = tid; i < (COMB_K * 128) / 4; i += 256)
        ((float4*)Bsf)[i] = ((const float4*)g_h1wt)[i];
    for (int i = tid; i < 128 * 8; i += 256) {
        int k = i >> 3, j = i & 7;
        sh3f[i] = (j < 7) ? h3w[j * 128 + k] : 0.f;
    }
    __syncthreads();

    int tx = tid & 15, ty = tid >> 4;

    // ---- GEMM1: h[128m][128n] = comb * h1wt  (packed n-pairs, k unrolled x2)
    {
        ull acc[8][4];
        #pragma unroll
        for (int i = 0; i < 8; i++)
            #pragma unroll
            for (int j = 0; j < 4; j++) acc[i][j] = 0ULL;
        for (int k = 0; k < COMB_K; k += 2) {
            ull bp0[4], bp1[4];
            float a0[8], a1[8];
            #pragma unroll
            for (int j = 0; j < 4; j++) {
                bp0[j] = Bsu[k * 64 + tx * 4 + j];
                bp1[j] = Bsu[(k + 1) * 64 + tx * 4 + j];
            }
            #pragma unroll
            for (int i = 0; i < 8; i++) {
                a0[i] = As[k * 129 + ty * 8 + i];
                a1[i] = As[(k + 1) * 129 + ty * 8 + i];
            }
            #pragma unroll
            for (int i = 0; i < 8; i++) {
                ull ad = pk_dup(a0[i]);
                #pragma unroll
                for (int j = 0; j < 4; j++) fma2(acc[i][j], ad, bp0[j]);
            }
            #pragma unroll
            for (int i = 0; i < 8; i++) {
                ull ad = pk_dup(a1[i]);
                #pragma unroll
                for (int j = 0; j < 4; j++) fma2(acc[i][j], ad, bp1[j]);
            }
        }
        // write pre-LN h (+bias) transposed into Hs[feature][m]
        #pragma unroll
        for (int j = 0; j < 4; j++) {
            int n = tx * 8 + j * 2;
            float bn0 = h1b[n], bn1 = h1b[n + 1];
            #pragma unroll
            for (int i = 0; i < 8; i++) {
                int m = ty * 8 + i;
                float lo, hi; unpk(acc[i][j], lo, hi);
                Hs[n * 129 + m]       = lo + bn0;
                Hs[(n + 1) * 129 + m] = hi + bn1;
            }
        }
    }
    __syncthreads();

    // load h2 weights (Bs free now)
    for (int i = tid; i < (128 * 128) / 4; i += 256)
        ((float4*)Bsf)[i] = ((const float4*)g_h2wt)[i];
    // LayerNorm + relu: 2 threads per sample row
    {
        int m = tid >> 1, half = tid & 1;
        int kb = half * 64;
        float s = 0.f, s2 = 0.f;
        for (int k = kb; k < kb + 64; k++) {
            float v = Hs[k * 129 + m];
            s += v; s2 += v * v;
        }
        s  += __shfl_xor_sync(0xffffffffu, s, 1);
        s2 += __shfl_xor_sync(0xffffffffu, s2, 1);
        float mu = s * (1.f / 128.f);
        float var = s2 * (1.f / 128.f) - mu * mu;
        float rs = rsqrtf(var + 1e-5f);
        for (int k = kb; k < kb + 64; k++) {
            float v = Hs[k * 129 + m];
            Hs[k * 129 + m] = fmaxf((v - mu) * rs * lng[k] + lnb[k], 0.f);
        }
    }
    __syncthreads();

    // ---- GEMM2: h2 = relu(h * h2wt + b)  (packed, k unrolled x2)
    {
        ull acc[8][4];
        #pragma unroll
        for (int i = 0; i < 8; i++)
            #pragma unroll
            for (int j = 0; j < 4; j++) acc[i][j] = 0ULL;
        for (int k = 0; k < 128; k += 2) {
            ull bp0[4], bp1[4];
            float a0[8], a1[8];
            #pragma unroll
            for (int j = 0; j < 4; j++) {
                bp0[j] = Bsu[k * 64 + tx * 4 + j];
                bp1[j] = Bsu[(k + 1) * 64 + tx * 4 + j];
            }
            #pragma unroll
            for (int i = 0; i < 8; i++) {
                a0[i] = Hs[k * 129 + ty * 8 + i];
                a1[i] = Hs[(k + 1) * 129 + ty * 8 + i];
            }
            #pragma unroll
            for (int i = 0; i < 8; i++) {
                ull ad = pk_dup(a0[i]);
                #pragma unroll
                for (int j = 0; j < 4; j++) fma2(acc[i][j], ad, bp0[j]);
            }
            #pragma unroll
            for (int i = 0; i < 8; i++) {
                ull ad = pk_dup(a1[i]);
                #pragma unroll
                for (int j = 0; j < 4; j++) fma2(acc[i][j], ad, bp1[j]);
            }
        }
        __syncthreads();   // done reading As (comb) — reuse as h2^T
        #pragma unroll
        for (int j = 0; j < 4; j++) {
            int n = tx * 8 + j * 2;
            float bn0 = h2b[n], bn1 = h2b[n + 1];
            #pragma unroll
            for (int i = 0; i < 8; i++) {
                int m = ty * 8 + i;
                float lo, hi; unpk(acc[i][j], lo, hi);
                As[n * 129 + m]       = fmaxf(lo + bn0, 0.f);
                As[(n + 1) * 129 + m] = fmaxf(hi + bn1, 0.f);
            }
        }
    }
    __syncthreads();

    // ---- h3: out[m][7]  (packed j-pairs via transposed sh3)
    if (tid < 128) {
        int m = tid;
        ull acc[4];
        #pragma unroll
        for (int j = 0; j < 4; j++) acc[j] = 0ULL;
        for (int k = 0; k < 128; k++) {
            ull ad = pk_dup(As[k * 129 + m]);
            #pragma unroll
            for (int j = 0; j < 4; j++) fma2(acc[j], ad, sh3u[k * 4 + j]);
        }
        float r[8];
        #pragma unroll
        for (int j = 0; j < 4; j++) unpk(acc[j], r[2 * j], r[2 * j + 1]);
        #pragma unroll
        for (int j = 0; j < 7; j++)
            out[(size_t)(m0 + m) * 7 + j] = r[j] + h3b[j];
    }
}

// ---------------- launch ----------------
extern "C" void kernel_launch(void* const* d_in, const int* in_sizes, int n_in,
                              void* d_out, int out_size)
{
    const int*   frame = (const int*)d_in[0];
    const int*   ccol  = (const int*)d_in[1];
    const int*   cobj  = (const int*)d_in[2];
    const float* c1w = (const float*)d_in[3];
    const float* c1b = (const float*)d_in[4];
    const float* c2w = (const float*)d_in[5];
    const float* c2b = (const float*)d_in[6];
    const float* c3w = (const float*)d_in[7];
    const float* c3b = (const float*)d_in[8];
    const float* pw  = (const float*)d_in[9];
    const float* pb  = (const float*)d_in[10];
    const float* h1w = (const float*)d_in[11];
    const float* h1b = (const float*)d_in[12];
    const float* lng = (const float*)d_in[13];
    const float* lnb = (const float*)d_in[14];
    const float* h2w = (const float*)d_in[15];
    const float* h2b = (const float*)d_in[16];
    const float* h3w = (const float*)d_in[17];
    const float* h3b = (const float*)d_in[18];
    float* out = (float*)d_out;

    cudaFuncSetAttribute(encode_kernel, cudaFuncAttributeMaxDynamicSharedMemorySize,
                         ENC_SMEM_FLOATS * (int)sizeof(float));
    cudaFuncSetAttribute(mlp_kernel, cudaFuncAttributeMaxDynamicSharedMemorySize,
                         MLP_SMEM_FLOATS * (int)sizeof(float));

    {
        int total = FEAT_K * 64 + COMB_K * 128 + 128 * 128;
        prep_kernel<<<(total + 255) / 256, 256>>>(pw, h1w, h2w);
    }
    encode_kernel<<<NSF / ENC_WARPS, ENC_THREADS,
                    ENC_SMEM_FLOATS * sizeof(float)>>>(
        frame, ccol, cobj, c1w, c1b, c2w, c2b, c3w, c3b);
    proj_kernel<<<NSF / 64, 256>>>(pb);
    mlp_kernel<<<NB / 128, 256, MLP_SMEM_FLOATS * sizeof(float)>>>(
        h1b, lng, lnb, h2b, h3w, h3b, out);
}

// round 10
// speedup vs baseline: 1.3215x; 1.0442x over previous
#include <cuda_runtime.h>
#include <cuda_bf16.h>
#include <math.h>

// ---------------- problem constants ----------------
#define NB 32768            // batch
#define NSF (2*NB)          // sample-frames
#define FEAT_K 592          // 578 padded to 16
#define COMB_K 136          // 132 padded to 8

typedef unsigned long long ull;

// ---------------- packed fp32x2 helpers (Blackwell FFMA2) ----------------
__device__ __forceinline__ ull pk_dup(float x) {
    ull r; unsigned u = __float_as_uint(x);
    asm("mov.b64 %0, {%1, %1};" : "=l"(r) : "r"(u));
    return r;
}
__device__ __forceinline__ void fma2(ull& d, ull a, ull b) {
    asm("fma.rn.f32x2 %0, %1, %2, %3;" : "=l"(d) : "l"(a), "l"(b), "l"(d));
}
__device__ __forceinline__ void unpk(ull v, float& lo, float& hi) {
    unsigned a, b;
    asm("mov.b64 {%0, %1}, %2;" : "=r"(a), "=r"(b) : "l"(v));
    lo = __uint_as_float(a); hi = __uint_as_float(b);
}

// ---------------- device scratch (static, no allocs) ----------------
__device__ float g_feats[(size_t)NSF * FEAT_K];   // ~155 MB
__device__ float g_emb[(size_t)NSF * 64];
__device__ int   g_dir[NSF];
__device__ float g_pos[NSF * 2];
__device__ float g_projwt[FEAT_K * 64];           // [k][e], zero-padded k>=578
__device__ float g_h1wt[COMB_K * 128];            // [k][o], zero-padded k>=132
__device__ float g_h2wt[128 * 128];               // [k][o]

// ---------------- kernel: weight transposes ----------------
__global__ void prep_kernel(const float* __restrict__ projw,
                            const float* __restrict__ h1w,
                            const float* __restrict__ h2w) {
    int i = blockIdx.x * 256 + threadIdx.x;
    const int N1 = FEAT_K * 64;
    const int N2 = COMB_K * 128;
    const int N3 = 128 * 128;
    if (i < N1) {
        int k = i / 64, e = i % 64;
        g_projwt[i] = (k < 578) ? projw[e * 578 + k] : 0.f;
    } else if (i < N1 + N2) {
        int j = i - N1;
        int k = j / 128, o = j % 128;
        g_h1wt[j] = (k < 132) ? h1w[o * 132 + k] : 0.f;
    } else if (i < N1 + N2 + N3) {
        int j = i - N1 - N2;
        int k = j / 128, o = j % 128;
        g_h2wt[j] = h2w[o * 128 + k];
    }
}

// ---------------- kernel: conv encoder (warp per sample-frame, packed f32x2) ----------------
// smem floats:
//  sw1p[192](pairs) sb1p[16](pairs) sw2p[2048](pairs) sb2p[32](pairs) sw3p[8192](pairs) sb3[64] = 10544
//  per warp (8): xind[488](dup) p1d[1152](dup) p2d[256](dup, real 2x2 only) = 1896
#define ENC_WARPS 8
#define ENC_THREADS (ENC_WARPS * 32)
#define ENC_WEIGHTS 10544
#define ENC_PERWARP 1896
#define ENC_SMEM_FLOATS (ENC_WEIGHTS + ENC_WARPS * ENC_PERWARP)

__global__ void __launch_bounds__(ENC_THREADS, 2) encode_kernel(
    const int* __restrict__ frame, const int* __restrict__ ccol, const int* __restrict__ cobj,
    const float* __restrict__ w1g, const float* __restrict__ b1g,
    const float* __restrict__ w2g, const float* __restrict__ b2g,
    const float* __restrict__ w3g, const float* __restrict__ b3g)
{
    extern __shared__ float smem[];
    float* sw1p = smem;                 // pairs: (r*8+cp)*2+sel  (r=ic*4+t; sel: +0 ch cp, +1 ch cp+8)
    float* sb1p = sw1p + 192;           // pairs: cp*2+sel
    float* sw2p = sb1p + 16;            // pairs: ((ic*4+t)*16+c)*2+sel  (sel: +0 ch c, +1 ch c+16)
    float* sb2p = sw2p + 2048;          // pairs: c*2+sel
    float* sw3p = sb2p + 32;            // pairs: ((ic*4+t)*32+l)*2+sel  (sel: +0 ch l, +1 ch l+32)
    float* sb3  = sw3p + 8192;
    float* swarp = sb3 + 64;

    int tid = threadIdx.x;
    for (int i = tid; i < 192; i += ENC_THREADS) {
        int c = i / 12, r = i % 12;
        int cp = c & 7, sel = c >> 3;
        sw1p[(r * 8 + cp) * 2 + sel] = w1g[i];
    }
    if (tid < 16) sb1p[(tid & 7) * 2 + (tid >> 3)] = b1g[tid];
    for (int i = tid; i < 2048; i += ENC_THREADS) {
        int oc = i >> 6, rem = i & 63;
        int c = oc & 15, sel = oc >> 4;
        sw2p[(rem * 16 + c) * 2 + sel] = w2g[i];
    }
    if (tid < 32) sb2p[(tid & 15) * 2 + (tid >> 4)] = b2g[tid];
    for (int i = tid; i < 8192; i += ENC_THREADS) {
        int oc = i >> 7, rem = i & 127;
        int l = oc & 31, sel = oc >> 5;
        sw3p[(rem * 32 + l) * 2 + sel] = w3g[i];
    }
    if (tid < 64) sb3[tid] = b3g[tid];
    __syncthreads();

    int warp = tid >> 5, lane = tid & 31;
    int sf = blockIdx.x * ENC_WARPS + warp;
    if (sf >= NSF) return;

    float* wbase = swarp + warp * ENC_PERWARP;
    float* xind = wbase;                // [3][9][9] duplicated pairs (486 used, 488 reserved)
    float* p1d  = wbase + 488;          // [16][6][6] duplicated pairs
    float* p2d  = wbase + 1640;         // [32][2][2] duplicated pairs (real only)
    float2* xinf2 = (float2*)xind;
    float2* p1f2 = (float2*)p1d;
    float2* p2f2 = (float2*)p2d;
    const ull* xinu = (const ull*)xind;
    const ull* p1du = (const ull*)p1d;
    const ull* p2du = (const ull*)p2d;
    const ull* w1u = (const ull*)sw1p;
    const ull* b1u = (const ull*)sb1p;
    const ull* w2u = (const ull*)sw2p;
    const ull* w3u = (const ull*)sw3p;

    const int* fb = frame + (size_t)sf * 147;

    // zero xind + p1d (p2d is fully written by conv2), then fill input interior (HWC -> CHW)
    for (int i = lane; i < 1640; i += 32) wbase[i] = 0.f;
    __syncwarp();
    for (int i = lane; i < 147; i += 32) {
        int y = i / 21, r = i % 21, x = r / 3, c = r % 3;
        float v = (float)fb[i];
        xinf2[c * 81 + (y + 1) * 9 + (x + 1)] = make_float2(v, v);
    }
    // dir/pos via ballot (first row-major position where ch0 == 10)
    {
        int v0 = fb[lane * 3];
        unsigned m0 = __ballot_sync(0xffffffffu, v0 == 10);
        int p2i = 32 + lane;
        int v1 = (p2i < 49) ? fb[p2i * 3] : 0;
        unsigned m1 = __ballot_sync(0xffffffffu, (p2i < 49) && (v1 == 10));
        if (lane == 0) {
            int idx = m0 ? (__ffs(m0) - 1) : (m1 ? (31 + __ffs(m1)) : -1);
            int d = 0; float py = 0.5f, px = 0.5f;
            if (idx >= 0) {
                d = fb[idx * 3 + 2] & 3;
                py = (float)(idx / 7) * (1.f / 6.f);
                px = (float)(idx % 7) * (1.f / 6.f);
            }
            g_dir[sf] = d;
            g_pos[sf * 2 + 0] = py;
            g_pos[sf * 2 + 1] = px;
        }
    }
    __syncwarp();

    // -------- conv1 (3->16, k2 pad1, out 8x8) + relu + pool2 -> p1d interior [16][4][4] dup
    // lane = (cp in 0..7, quad in 0..3); channel pair (cp, cp+8), quadrant of 4x4 conv outputs
    {
        int cp = lane & 7, quad = lane >> 3;
        int qy = quad >> 1, qx = quad & 1;
        ull w[12];
        #pragma unroll
        for (int r = 0; r < 12; r++) w[r] = w1u[r * 8 + cp];
        float blo, bhi;
        { ull bp = b1u[cp]; unpk(bp, blo, bhi); }
        ull acc[16];
        #pragma unroll
        for (int i = 0; i < 16; i++) acc[i] = 0ULL;
        #pragma unroll
        for (int ic = 0; ic < 3; ic++) {
            const ull* xb = xinu + ic * 81 + (4 * qy) * 9 + 4 * qx;
            ull in[5][5];
            #pragma unroll
            for (int r = 0; r < 5; r++)
                #pragma unroll
                for (int x = 0; x < 5; x++) in[r][x] = xb[r * 9 + x];
            ull w0 = w[ic * 4 + 0], w1 = w[ic * 4 + 1];
            ull w2 = w[ic * 4 + 2], w3 = w[ic * 4 + 3];
            #pragma unroll
            for (int oy = 0; oy < 4; oy++)
                #pragma unroll
                for (int ox = 0; ox < 4; ox++) {
                    ull* a = &acc[oy * 4 + ox];
                    fma2(*a, w0, in[oy][ox]);
                    fma2(*a, w1, in[oy][ox + 1]);
                    fma2(*a, w2, in[oy + 1][ox]);
                    fma2(*a, w3, in[oy + 1][ox + 1]);
                }
        }
        #pragma unroll
        for (int pr = 0; pr < 2; pr++)
            #pragma unroll
            for (int pc = 0; pc < 2; pc++) {
                float l0, h0, l1, h1, l2, h2, l3, h3;
                unpk(acc[(2 * pr) * 4 + 2 * pc],         l0, h0);
                unpk(acc[(2 * pr) * 4 + 2 * pc + 1],     l1, h1);
                unpk(acc[(2 * pr + 1) * 4 + 2 * pc],     l2, h2);
                unpk(acc[(2 * pr + 1) * 4 + 2 * pc + 1], l3, h3);
                float mlo = fmaxf(fmaxf(l0, l1), fmaxf(l2, l3));
                float mhi = fmaxf(fmaxf(h0, h1), fmaxf(h2, h3));
                float vlo = fmaxf(mlo + blo, 0.f);
                float vhi = fmaxf(mhi + bhi, 0.f);
                int py = 2 * qy + pr, px = 2 * qx + pc;
                p1f2[cp * 36 + (py + 1) * 6 + (px + 1)]       = make_float2(vlo, vlo);
                p1f2[(cp + 8) * 36 + (py + 1) * 6 + (px + 1)] = make_float2(vhi, vhi);
            }
    }
    __syncwarp();

    // -------- conv2 (16->32) + relu + pool -> p2d [32][2][2] dup (real only)
    // lane = (c in 0..15, h in 0..1); channel pair (c, c+16), conv-output rows {2h, 2h+1}
    {
        int c = lane & 15, h = lane >> 4;
        ull acc[8];
        #pragma unroll
        for (int i = 0; i < 8; i++) acc[i] = 0ULL;
        #pragma unroll 4
        for (int ic = 0; ic < 16; ic++) {
            ull in[3][5];
            #pragma unroll
            for (int r = 0; r < 3; r++)
                #pragma unroll
                for (int x = 0; x < 5; x++)
                    in[r][x] = p1du[ic * 36 + (2 * h + r) * 6 + x];
            ull wa = w2u[(ic * 4 + 0) * 16 + c];
            ull wb = w2u[(ic * 4 + 1) * 16 + c];
            ull wc = w2u[(ic * 4 + 2) * 16 + c];
            ull wd = w2u[(ic * 4 + 3) * 16 + c];
            #pragma unroll
            for (int ry = 0; ry < 2; ry++)
                #pragma unroll
                for (int ox = 0; ox < 4; ox++) {
                    ull* a = &acc[ry * 4 + ox];
                    fma2(*a, wa, in[ry][ox]);
                    fma2(*a, wb, in[ry][ox + 1]);
                    fma2(*a, wc, in[ry + 1][ox]);
                    fma2(*a, wd, in[ry + 1][ox + 1]);
                }
        }
        ull bp = ((const ull*)sb2p)[c];
        float blo, bhi; unpk(bp, blo, bhi);
        #pragma unroll
        for (int px = 0; px < 2; px++) {
            float l0, h0, l1, h1, l2, h2, l3, h3;
            unpk(acc[0 * 4 + 2 * px],     l0, h0);
            unpk(acc[0 * 4 + 2 * px + 1], l1, h1);
            unpk(acc[1 * 4 + 2 * px],     l2, h2);
            unpk(acc[1 * 4 + 2 * px + 1], l3, h3);
            float mlo = fmaxf(fmaxf(l0, l1), fmaxf(l2, l3));
            float mhi = fmaxf(fmaxf(h0, h1), fmaxf(h2, h3));
            float vlo = fmaxf(mlo + blo, 0.f);
            float vhi = fmaxf(mhi + bhi, 0.f);
            p2f2[c * 4 + h * 2 + px]        = make_float2(vlo, vlo);
            p2f2[(c + 16) * 4 + h * 2 + px] = make_float2(vhi, vhi);
        }
    }
    __syncwarp();

    // -------- conv3 (32->64, out 3x3) + relu -> feats; SCATTER from 4 real pixels.
    {
        ull a[9];
        #pragma unroll
        for (int i = 0; i < 9; i++) a[i] = 0ULL;
        #pragma unroll 4
        for (int ic = 0; ic < 32; ic++) {
            ull v00 = p2du[ic * 4 + 0];
            ull v01 = p2du[ic * 4 + 1];
            ull v10 = p2du[ic * 4 + 2];
            ull v11 = p2du[ic * 4 + 3];
            ull w00 = w3u[(ic * 4 + 0) * 32 + lane];   // w[0][0]
            ull w01 = w3u[(ic * 4 + 1) * 32 + lane];   // w[0][1]
            ull w10 = w3u[(ic * 4 + 2) * 32 + lane];   // w[1][0]
            ull w11 = w3u[(ic * 4 + 3) * 32 + lane];   // w[1][1]
            fma2(a[0], w11, v00); fma2(a[1], w10, v00);
            fma2(a[3], w01, v00); fma2(a[4], w00, v00);
            fma2(a[1], w11, v01); fma2(a[2], w10, v01);
            fma2(a[4], w01, v01); fma2(a[5], w00, v01);
            fma2(a[3], w11, v10); fma2(a[4], w10, v10);
            fma2(a[6], w01, v10); fma2(a[7], w00, v10);
            fma2(a[4], w11, v11); fma2(a[5], w10, v11);
            fma2(a[7], w01, v11); fma2(a[8], w00, v11);
        }
        float* fbase = g_feats + (size_t)sf * FEAT_K;
        float b0 = sb3[lane], b1v = sb3[lane + 32];
        #pragma unroll
        for (int p = 0; p < 9; p++) {
            float lo, hi; unpk(a[p], lo, hi);
            fbase[lane * 9 + p]        = fmaxf(lo + b0, 0.f);
            fbase[(lane + 32) * 9 + p] = fmaxf(hi + b1v, 0.f);
        }
        if (lane == 0) {
            fbase[576] = (float)ccol[sf];
            fbase[577] = (float)cobj[sf];
        }
        if (lane < 14) fbase[578 + lane] = 0.f;
    }
}

// ---------------- kernel: proj GEMM  emb[2B,64] = relu(feats * Wt + b), packed ----------------
// block: 128 m x 64 n, 256 threads, thread tile 4m x 8n (4 n-pairs)
__global__ void __launch_bounds__(256) proj_kernel(const float* __restrict__ projb)
{
    __shared__ float As[16][132];      // [k][m]
    __shared__ ull   Bsu[16 * 32];     // [k][slot]; slot(np) = (np&3)*8 + (np>>2)
    int tid = threadIdx.x;
    int m0 = blockIdx.x * 128;
    int tx = tid & 7, ty = tid >> 3;   // tx: n-groups (8n each), ty: 0..31 (4m each)
    ull acc[4][4];
    #pragma unroll
    for (int i = 0; i < 4; i++)
        #pragma unroll
        for (int j = 0; j < 4; j++) acc[i][j] = 0ULL;

    for (int k0 = 0; k0 < FEAT_K; k0 += 16) {
        {
            int m = tid >> 1, kq = (tid & 1) * 8;
            const float* src = g_feats + (size_t)(m0 + m) * FEAT_K + k0 + kq;
            float4 a0 = *reinterpret_cast<const float4*>(src);
            float4 a1 = *reinterpret_cast<const float4*>(src + 4);
            As[kq + 0][m] = a0.x; As[kq + 1][m] = a0.y; As[kq + 2][m] = a0.z; As[kq + 3][m] = a0.w;
            As[kq + 4][m] = a1.x; As[kq + 5][m] = a1.y; As[kq + 6][m] = a1.z; As[kq + 7][m] = a1.w;
        }
        {
            int k = tid >> 4, q = tid & 15;
            float4 bv = *reinterpret_cast<const float4*>(g_projwt + (k0 + k) * 64 + q * 4);
            int np0 = 2 * q, np1 = 2 * q + 1;
            int s0 = (np0 & 3) * 8 + (np0 >> 2);
            int s1 = (np1 & 3) * 8 + (np1 >> 2);
            float2* bf2 = (float2*)Bsu;
            bf2[k * 32 + s0] = make_float2(bv.x, bv.y);
            bf2[k * 32 + s1] = make_float2(bv.z, bv.w);
        }
        __syncthreads();
        #pragma unroll
        for (int k = 0; k < 16; k++) {
            ull bp[4];
            #pragma unroll
            for (int j = 0; j < 4; j++) bp[j] = Bsu[k * 32 + j * 8 + tx];   // np = tx*4+j
            float a[4];
            #pragma unroll
            for (int i = 0; i < 4; i++) a[i] = As[k][ty * 4 + i];
            #pragma unroll
            for (int i = 0; i < 4; i++) {
                ull ad = pk_dup(a[i]);
                #pragma unroll
                for (int j = 0; j < 4; j++) fma2(acc[i][j], ad, bp[j]);
            }
        }
        __syncthreads();
    }
    #pragma unroll
    for (int i = 0; i < 4; i++) {
        int m = m0 + ty * 4 + i;
        #pragma unroll
        for (int j = 0; j < 4; j++) {
            int n = tx * 8 + 2 * j;
            float lo, hi; unpk(acc[i][j], lo, hi);
            g_emb[(size_t)m * 64 + n]     = fmaxf(lo + projb[n], 0.f);
            g_emb[(size_t)m * 64 + n + 1] = fmaxf(hi + projb[n + 1], 0.f);
        }
    }
}

// ---------------- kernel: fused comb + MLP (h1 -> LN -> relu -> h2 -> relu -> h3), packed ----------------
// smem floats: As[136*129] (comb -> Hs -> h2T overlay) + Bs[68*128] (half-K weight staging) + sh3[128*8]
#define MLP_AS (136 * 129)
#define MLP_BS (68 * 128)
#define MLP_SH3 (128 * 8)
#define MLP_SMEM_FLOATS (MLP_AS + MLP_BS + MLP_SH3)

__global__ void __launch_bounds__(256, 2) mlp_kernel(
    const float* __restrict__ h1b, const float* __restrict__ lng, const float* __restrict__ lnb,
    const float* __restrict__ h2b, const float* __restrict__ h3w, const float* __restrict__ h3b,
    float* __restrict__ out)
{
    extern __shared__ float smem[];
    float* As   = smem;                 // comb^T [k][m] stride 129; later Hs, later h2^T
    float* Bsf  = As + MLP_AS;          // weight staging [k-half][slot]
    float* sh3f = Bsf + MLP_BS;         // h3 transposed [k][8] (j<7 real)
    ull* Bsu  = (ull*)Bsf;
    ull* sh3u = (ull*)sh3f;

    int tid = threadIdx.x;
    int m0 = blockIdx.x * 128;
    int tx = tid & 15, ty = tid >> 4;

    // Bs slot remap: slot(np) = (np&3)*16 + (np>>2); compute reads Bsu[k*64 + j*16 + tx] (np = tx*4+j)
    auto load_bs_half = [&](const float* wsrc, int rows) {
        for (int i = tid; i < rows * 32; i += 256) {
            int k = i >> 5, q = i & 31;
            float4 bv = *reinterpret_cast<const float4*>(wsrc + k * 128 + q * 4);
            int np0 = 2 * q, np1 = 2 * q + 1;
            int s0 = (np0 & 3) * 16 + (np0 >> 2);
            int s1 = (np1 & 3) * 16 + (np1 >> 2);
            float2* bf2 = (float2*)Bsu;
            bf2[k * 64 + s0] = make_float2(bv.x, bv.y);
            bf2[k * 64 + s1] = make_float2(bv.z, bv.w);
        }
    };

    // ---- build comb directly into As; stage sh3; stage h1 weights half 0
    for (int i = tid; i < 128 * COMB_K; i += 256) {
        int m = i / COMB_K, k = i - m * COMB_K;
        int b = m0 + m;
        float v;
        if (k < 64)       v = g_emb[(size_t)b * 64 + k];
        else if (k < 128) v = g_emb[(size_t)(NB + b) * 64 + (k - 64)];
        else if (k < 130) {
            int delta = ((g_dir[NB + b] - g_dir[b]) + 4) & 3;
            float ang = (float)delta * (2.0f * 3.14159f / 4.0f);
            v = (k == 128) ? sinf(ang) : cosf(ang);
        }
        else if (k == 130) v = g_pos[(NB + b) * 2 + 0] - g_pos[b * 2 + 0];
        else if (k == 131) v = g_pos[(NB + b) * 2 + 1] - g_pos[b * 2 + 1];
        else v = 0.f;
        As[k * 129 + m] = v;
    }
    for (int i = tid; i < 128 * 8; i += 256) {
        int k = i >> 3, j = i & 7;
        sh3f[i] = (j < 7) ? h3w[j * 128 + k] : 0.f;
    }
    load_bs_half(g_h1wt, 68);
    __syncthreads();

    // ---- GEMM1: h[128m][128n] = comb * h1wt  (half-K staged, k unrolled x2)
    ull acc[8][4];
    #pragma unroll
    for (int i = 0; i < 8; i++)
        #pragma unroll
        for (int j = 0; j < 4; j++) acc[i][j] = 0ULL;
    #pragma unroll 1
    for (int half = 0; half < 2; half++) {
        if (half) {
            __syncthreads();
            load_bs_half(g_h1wt + 68 * 128, 68);
            __syncthreads();
        }
        int kb = half * 68;
        for (int k = 0; k < 68; k += 2) {
            ull bp0[4], bp1[4];
            float a0[8], a1[8];
            #pragma unroll
            for (int j = 0; j < 4; j++) {
                bp0[j] = Bsu[k * 64 + j * 16 + tx];
                bp1[j] = Bsu[(k + 1) * 64 + j * 16 + tx];
            }
            #pragma unroll
            for (int i = 0; i < 8; i++) {
                a0[i] = As[(kb + k) * 129 + ty * 8 + i];
                a1[i] = As[(kb + k + 1) * 129 + ty * 8 + i];
            }
            #pragma unroll
            for (int i = 0; i < 8; i++) {
                ull ad = pk_dup(a0[i]);
                #pragma unroll
                for (int j = 0; j < 4; j++) fma2(acc[i][j], ad, bp0[j]);
            }
            #pragma unroll
            for (int i = 0; i < 8; i++) {
                ull ad = pk_dup(a1[i]);
                #pragma unroll
                for (int j = 0; j < 4; j++) fma2(acc[i][j], ad, bp1[j]);
            }
        }
    }
    __syncthreads();   // all reads of As (comb) done

    // ---- write pre-LN h (+bias) transposed into As region (Hs[feature][m]); stage h2 half 0
    float* Hs = As;
    #pragma unroll
    for (int j = 0; j < 4; j++) {
        int n = tx * 8 + 2 * j;      // np = tx*4+j -> n pair (n, n+1)
        float bn0 = h1b[n], bn1 = h1b[n + 1];
        #pragma unroll
        for (int i = 0; i < 8; i++) {
            int m = ty * 8 + i;
            float lo, hi; unpk(acc[i][j], lo, hi);
            Hs[n * 129 + m]       = lo + bn0;
            Hs[(n + 1) * 129 + m] = hi + bn1;
        }
    }
    load_bs_half(g_h2wt, 64);
    __syncthreads();

    // ---- LayerNorm + relu: 2 threads per sample row
    {
        int m = tid >> 1, halfr = tid & 1;
        int kb = halfr * 64;
        float s = 0.f, s2 = 0.f;
        for (int k = kb; k < kb + 64; k++) {
            float v = Hs[k * 129 + m];
            s += v; s2 += v * v;
        }
        s  += __shfl_xor_sync(0xffffffffu, s, 1);
        s2 += __shfl_xor_sync(0xffffffffu, s2, 1);
        float mu = s * (1.f / 128.f);
        float var = s2 * (1.f / 128.f) - mu * mu;
        float rs = rsqrtf(var + 1e-5f);
        for (int k = kb; k < kb + 64; k++) {
            float v = Hs[k * 129 + m];
            Hs[k * 129 + m] = fmaxf((v - mu) * rs * lng[k] + lnb[k], 0.f);
        }
    }
    __syncthreads();

    // ---- GEMM2: h2 = relu(h * h2wt + b)  (half-K staged, k unrolled x2)
    ull acc2[8][4];
    #pragma unroll
    for (int i = 0; i < 8; i++)
        #pragma unroll
        for (int j = 0; j < 4; j++) acc2[i][j] = 0ULL;
    #pragma unroll 1
    for (int half = 0; half < 2; half++) {
        if (half) {
            __syncthreads();
            load_bs_half(g_h2wt + 64 * 128, 64);
            __syncthreads();
        }
        int kb = half * 64;
        for (int k = 0; k < 64; k += 2) {
            ull bp0[4], bp1[4];
            float a0[8], a1[8];
            #pragma unroll
            for (int j = 0; j < 4; j++) {
                bp0[j] = Bsu[k * 64 + j * 16 + tx];
                bp1[j] = Bsu[(k + 1) * 64 + j * 16 + tx];
            }
            #pragma unroll
            for (int i = 0; i < 8; i++) {
                a0[i] = Hs[(kb + k) * 129 + ty * 8 + i];
                a1[i] = Hs[(kb + k + 1) * 129 + ty * 8 + i];
            }
            #pragma unroll
            for (int i = 0; i < 8; i++) {
                ull ad = pk_dup(a0[i]);
                #pragma unroll
                for (int j = 0; j < 4; j++) fma2(acc2[i][j], ad, bp0[j]);
            }
            #pragma unroll
            for (int i = 0; i < 8; i++) {
                ull ad = pk_dup(a1[i]);
                #pragma unroll
                for (int j = 0; j < 4; j++) fma2(acc2[i][j], ad, bp1[j]);
            }
        }
    }
    __syncthreads();   // all reads of Hs done

    // ---- write h2 (relu) transposed into As region again
    #pragma unroll
    for (int j = 0; j < 4; j++) {
        int n = tx * 8 + 2 * j;
        float bn0 = h2b[n], bn1 = h2b[n + 1];
        #pragma unroll
        for (int i = 0; i < 8; i++) {
            int m = ty * 8 + i;
            float lo, hi; unpk(acc2[i][j], lo, hi);
            As[n * 129 + m]       = fmaxf(lo + bn0, 0.f);
            As[(n + 1) * 129 + m] = fmaxf(hi + bn1, 0.f);
        }
    }
    __syncthreads();

    // ---- h3: out[m][7]  (packed j-pairs via transposed sh3)
    if (tid < 128) {
        int m = tid;
        ull acc3[4];
        #pragma unroll
        for (int j = 0; j < 4; j++) acc3[j] = 0ULL;
        for (int k = 0; k < 128; k++) {
            ull ad = pk_dup(As[k * 129 + m]);
            #pragma unroll
            for (int j = 0; j < 4; j++) fma2(acc3[j], ad, sh3u[k * 4 + j]);
        }
        float r[8];
        #pragma unroll
        for (int j = 0; j < 4; j++) unpk(acc3[j], r[2 * j], r[2 * j + 1]);
        #pragma unroll
        for (int j = 0; j < 7; j++)
            out[(size_t)(m0 + m) * 7 + j] = r[j] + h3b[j];
    }
}

// ---------------- launch ----------------
extern "C" void kernel_launch(void* const* d_in, const int* in_sizes, int n_in,
                              void* d_out, int out_size)
{
    const int*   frame = (const int*)d_in[0];
    const int*   ccol  = (const int*)d_in[1];
    const int*   cobj  = (const int*)d_in[2];
    const float* c1w = (const float*)d_in[3];
    const float* c1b = (const float*)d_in[4];
    const float* c2w = (const float*)d_in[5];
    const float* c2b = (const float*)d_in[6];
    const float* c3w = (const float*)d_in[7];
    const float* c3b = (const float*)d_in[8];
    const float* pw  = (const float*)d_in[9];
    const float* pb  = (const float*)d_in[10];
    const float* h1w = (const float*)d_in[11];
    const float* h1b = (const float*)d_in[12];
    const float* lng = (const float*)d_in[13];
    const float* lnb = (const float*)d_in[14];
    const float* h2w = (const float*)d_in[15];
    const float* h2b = (const float*)d_in[16];
    const float* h3w = (const float*)d_in[17];
    const float* h3b = (const float*)d_in[18];
    float* out = (float*)d_out;

    cudaFuncSetAttribute(encode_kernel, cudaFuncAttributeMaxDynamicSharedMemorySize,
                         ENC_SMEM_FLOATS * (int)sizeof(float));
    cudaFuncSetAttribute(mlp_kernel, cudaFuncAttributeMaxDynamicSharedMemorySize,
                         MLP_SMEM_FLOATS * (int)sizeof(float));

    {
        int total = FEAT_K * 64 + COMB_K * 128 + 128 * 128;
        prep_kernel<<<(total + 255) / 256, 256>>>(pw, h1w, h2w);
    }
    encode_kernel<<<NSF / ENC_WARPS, ENC_THREADS,
                    ENC_SMEM_FLOATS * sizeof(float)>>>(
        frame, ccol, cobj, c1w, c1b, c2w, c2b, c3w, c3b);
    proj_kernel<<<NSF / 128, 256>>>(pb);
    mlp_kernel<<<NB / 128, 256, MLP_SMEM_FLOATS * sizeof(float)>>>(
        h1b, lng, lnb, h2b, h3w, h3b, out);
}

// round 12
// speedup vs baseline: 1.4846x; 1.1234x over previous
#include <cuda_runtime.h>
#include <cuda_bf16.h>
#include <math.h>

// ---------------- problem constants ----------------
#define NB 32768            // batch
#define NSF (2*NB)          // sample-frames
#define FEAT_K 592          // 578 padded to 16
#define COMB_K 136          // 132 padded to 8

typedef unsigned long long ull;

// ---------------- packed fp32x2 helpers (Blackwell FFMA2) ----------------
__device__ __forceinline__ ull pk_dup(float x) {
    ull r; unsigned u = __float_as_uint(x);
    asm("mov.b64 %0, {%1, %1};" : "=l"(r) : "r"(u));
    return r;
}
__device__ __forceinline__ void fma2(ull& d, ull a, ull b) {
    asm("fma.rn.f32x2 %0, %1, %2, %3;" : "=l"(d) : "l"(a), "l"(b), "l"(d));
}
__device__ __forceinline__ void unpk(ull v, float& lo, float& hi) {
    unsigned a, b;
    asm("mov.b64 {%0, %1}, %2;" : "=r"(a), "=r"(b) : "l"(v));
    lo = __uint_as_float(a); hi = __uint_as_float(b);
}
__device__ __forceinline__ ulonglong2 ld2(const ull* p) {   // p must be 16B aligned
    return *reinterpret_cast<const ulonglong2*>(p);
}

// ---------------- device scratch (static, no allocs) ----------------
__device__ float g_feats[(size_t)NSF * FEAT_K];   // ~155 MB
__device__ float g_emb[(size_t)NSF * 64];
__device__ int   g_dir[NSF];
__device__ float g_pos[NSF * 2];
__device__ float g_projwt[FEAT_K * 64];           // [k][e], zero-padded k>=578
__device__ float g_h1wt[COMB_K * 128];            // [k][o], zero-padded k>=132
__device__ float g_h2wt[128 * 128];               // [k][o]

// ---------------- kernel: weight transposes ----------------
__global__ void prep_kernel(const float* __restrict__ projw,
                            const float* __restrict__ h1w,
                            const float* __restrict__ h2w) {
    int i = blockIdx.x * 256 + threadIdx.x;
    const int N1 = FEAT_K * 64;
    const int N2 = COMB_K * 128;
    const int N3 = 128 * 128;
    if (i < N1) {
        int k = i / 64, e = i % 64;
        g_projwt[i] = (k < 578) ? projw[e * 578 + k] : 0.f;
    } else if (i < N1 + N2) {
        int j = i - N1;
        int k = j / 128, o = j % 128;
        g_h1wt[j] = (k < 132) ? h1w[o * 132 + k] : 0.f;
    } else if (i < N1 + N2 + N3) {
        int j = i - N1 - N2;
        int k = j / 128, o = j % 128;
        g_h2wt[j] = h2w[o * 128 + k];
    }
}

// ---------------- kernel: conv encoder (warp per sample-frame, packed f32x2, LDS.128) ----------------
// smem floats:
//  sw1p[192] sb1p[16] sw2p[2048] sb2p[32] sw3p[8192] sb3[64] = 10544  (all pair layouts, .128-friendly)
//  per warp (16): xind[540]([3][9][10] pairs, dup) p1d[1152]([16][6][6] pairs) p2d[256]([32][2][2] pairs) = 1948
#define ENC_WARPS 16
#define ENC_THREADS (ENC_WARPS * 32)
#define ENC_WEIGHTS 10544
#define ENC_PERWARP 1948
#define ENC_SMEM_FLOATS (ENC_WEIGHTS + ENC_WARPS * ENC_PERWARP)

__global__ void __launch_bounds__(ENC_THREADS, 1) encode_kernel(
    const int* __restrict__ frame, const int* __restrict__ ccol, const int* __restrict__ cobj,
    const float* __restrict__ w1g, const float* __restrict__ b1g,
    const float* __restrict__ w2g, const float* __restrict__ b2g,
    const float* __restrict__ w3g, const float* __restrict__ b3g)
{
    extern __shared__ float smem[];
    float* sw1p = smem;                 // pairs: cp*12 + r        (r = ic*4+t; sel: +0 ch cp, +1 ch cp+8)
    float* sb1p = sw1p + 192;           // pairs: cp
    float* sw2p = sb1p + 16;            // pairs: (ic*16+c)*4 + t  (sel: +0 ch c, +1 ch c+16)
    float* sb2p = sw2p + 2048;          // pairs: c
    float* sw3p = sb2p + 32;            // pairs: (ic*32+l)*4 + t  (sel: +0 ch l, +1 ch l+32)
    float* sb3  = sw3p + 8192;
    float* swarp = sb3 + 64;

    int tid = threadIdx.x;
    for (int i = tid; i < 192; i += ENC_THREADS) {
        int c = i / 12, r = i % 12;
        int cp = c & 7, sel = c >> 3;
        sw1p[(cp * 12 + r) * 2 + sel] = w1g[i];
    }
    if (tid < 16) sb1p[(tid & 7) * 2 + (tid >> 3)] = b1g[tid];
    for (int i = tid; i < 2048; i += ENC_THREADS) {
        int oc = i >> 6, rem = i & 63;          // rem = ic*4+t
        int ic = rem >> 2, t = rem & 3;
        int c = oc & 15, sel = oc >> 4;
        sw2p[(((ic * 16 + c) * 4) + t) * 2 + sel] = w2g[i];
    }
    if (tid < 32) sb2p[(tid & 15) * 2 + (tid >> 4)] = b2g[tid];
    for (int i = tid; i < 8192; i += ENC_THREADS) {
        int oc = i >> 7, rem = i & 127;         // rem = ic*4+t
        int ic = rem >> 2, t = rem & 3;
        int l = oc & 31, sel = oc >> 5;
        sw3p[(((ic * 32 + l) * 4) + t) * 2 + sel] = w3g[i];
    }
    if (tid < 64) sb3[tid] = b3g[tid];
    __syncthreads();

    int warp = tid >> 5, lane = tid & 31;
    int sf = blockIdx.x * ENC_WARPS + warp;
    if (sf >= NSF) return;

    float* wbase = swarp + warp * ENC_PERWARP;
    float* xind = wbase;                // [3][9][10] duplicated pairs (540 floats)
    float* p1d  = wbase + 540;          // [16][6][6] duplicated pairs
    float* p2d  = wbase + 1692;         // [32][2][2] duplicated pairs (real only)
    float2* xinf2 = (float2*)xind;
    float2* p1f2 = (float2*)p1d;
    float2* p2f2 = (float2*)p2d;
    const ull* xinu = (const ull*)xind;
    const ull* p1du = (const ull*)p1d;
    const ull* p2du = (const ull*)p2d;
    const ull* w1u = (const ull*)sw1p;
    const ull* b1u = (const ull*)sb1p;
    const ull* w2u = (const ull*)sw2p;
    const ull* w3u = (const ull*)sw3p;

    const int* fb = frame + (size_t)sf * 147;

    // zero xind + p1d as pairs (p2d is fully written by conv2)
    for (int i = lane; i < 846; i += 32) ((float2*)wbase)[i] = make_float2(0.f, 0.f);
    __syncwarp();
    for (int i = lane; i < 147; i += 32) {
        int y = i / 21, r = i % 21, x = r / 3, c = r % 3;
        float v = (float)fb[i];
        xinf2[c * 90 + (y + 1) * 10 + (x + 1)] = make_float2(v, v);
    }
    // dir/pos via ballot (first row-major position where ch0 == 10)
    {
        int v0 = fb[lane * 3];
        unsigned m0 = __ballot_sync(0xffffffffu, v0 == 10);
        int p2i = 32 + lane;
        int v1 = (p2i < 49) ? fb[p2i * 3] : 0;
        unsigned m1 = __ballot_sync(0xffffffffu, (p2i < 49) && (v1 == 10));
        if (lane == 0) {
            int idx = m0 ? (__ffs(m0) - 1) : (m1 ? (31 + __ffs(m1)) : -1);
            int d = 0; float py = 0.5f, px = 0.5f;
            if (idx >= 0) {
                d = fb[idx * 3 + 2] & 3;
                py = (float)(idx / 7) * (1.f / 6.f);
                px = (float)(idx % 7) * (1.f / 6.f);
            }
            g_dir[sf] = d;
            g_pos[sf * 2 + 0] = py;
            g_pos[sf * 2 + 1] = px;
        }
    }
    __syncwarp();

    // -------- conv1 (3->16, k2 pad1, out 8x8) + relu + pool2 -> p1d interior [16][4][4]
    // lane = (cp in 0..7, quad in 0..3); channel pair (cp, cp+8), quadrant of 4x4 conv outputs
    {
        int cp = lane & 7, quad = lane >> 3;
        int qy = quad >> 1, qx = quad & 1;
        ull w[12];
        #pragma unroll
        for (int r2 = 0; r2 < 6; r2++) {
            ulonglong2 t = ld2(w1u + cp * 12 + r2 * 2);
            w[r2 * 2] = t.x; w[r2 * 2 + 1] = t.y;
        }
        float blo, bhi;
        { ull bp = b1u[cp]; unpk(bp, blo, bhi); }
        ull acc[16];
        #pragma unroll
        for (int i = 0; i < 16; i++) acc[i] = 0ULL;
        #pragma unroll
        for (int ic = 0; ic < 3; ic++) {
            const ull* xb = xinu + ic * 90 + (4 * qy) * 10 + 4 * qx;   // even offset
            ull in[5][5];
            #pragma unroll
            for (int r = 0; r < 5; r++) {
                ulonglong2 t0 = ld2(xb + r * 10);
                ulonglong2 t1 = ld2(xb + r * 10 + 2);
                in[r][0] = t0.x; in[r][1] = t0.y;
                in[r][2] = t1.x; in[r][3] = t1.y;
                in[r][4] = xb[r * 10 + 4];
            }
            ull w0 = w[ic * 4 + 0], w1 = w[ic * 4 + 1];
            ull w2 = w[ic * 4 + 2], w3 = w[ic * 4 + 3];
            #pragma unroll
            for (int oy = 0; oy < 4; oy++)
                #pragma unroll
                for (int ox = 0; ox < 4; ox++) {
                    ull* a = &acc[oy * 4 + ox];
                    fma2(*a, w0, in[oy][ox]);
                    fma2(*a, w1, in[oy][ox + 1]);
                    fma2(*a, w2, in[oy + 1][ox]);
                    fma2(*a, w3, in[oy + 1][ox + 1]);
                }
        }
        #pragma unroll
        for (int pr = 0; pr < 2; pr++)
            #pragma unroll
            for (int pc = 0; pc < 2; pc++) {
                float l0, h0, l1, h1, l2, h2, l3, h3;
                unpk(acc[(2 * pr) * 4 + 2 * pc],         l0, h0);
                unpk(acc[(2 * pr) * 4 + 2 * pc + 1],     l1, h1);
                unpk(acc[(2 * pr + 1) * 4 + 2 * pc],     l2, h2);
                unpk(acc[(2 * pr + 1) * 4 + 2 * pc + 1], l3, h3);
                float mlo = fmaxf(fmaxf(l0, l1), fmaxf(l2, l3));
                float mhi = fmaxf(fmaxf(h0, h1), fmaxf(h2, h3));
                float vlo = fmaxf(mlo + blo, 0.f);
                float vhi = fmaxf(mhi + bhi, 0.f);
                int py = 2 * qy + pr, px = 2 * qx + pc;
                p1f2[cp * 36 + (py + 1) * 6 + (px + 1)]       = make_float2(vlo, vlo);
                p1f2[(cp + 8) * 36 + (py + 1) * 6 + (px + 1)] = make_float2(vhi, vhi);
            }
    }
    __syncwarp();

    // -------- conv2 (16->32) + relu + pool -> p2d [32][2][2] (real only)
    // lane = (c in 0..15, h in 0..1); channel pair (c, c+16), conv-output rows {2h, 2h+1}
    {
        int c = lane & 15, h = lane >> 4;
        ull acc[8];
        #pragma unroll
        for (int i = 0; i < 8; i++) acc[i] = 0ULL;
        #pragma unroll 4
        for (int ic = 0; ic < 16; ic++) {
            ull in[3][5];
            #pragma unroll
            for (int r = 0; r < 3; r++) {
                const ull* rb = p1du + ic * 36 + (2 * h + r) * 6;   // even offset
                ulonglong2 t0 = ld2(rb);
                ulonglong2 t1 = ld2(rb + 2);
                in[r][0] = t0.x; in[r][1] = t0.y;
                in[r][2] = t1.x; in[r][3] = t1.y;
                in[r][4] = rb[4];
            }
            const ull* wb = w2u + (ic * 16 + c) * 4;                // even offset
            ulonglong2 wt0 = ld2(wb);
            ulonglong2 wt1 = ld2(wb + 2);
            ull wa = wt0.x, wbp = wt0.y, wc = wt1.x, wd = wt1.y;
            #pragma unroll
            for (int ry = 0; ry < 2; ry++)
                #pragma unroll
                for (int ox = 0; ox < 4; ox++) {
                    ull* a = &acc[ry * 4 + ox];
                    fma2(*a, wa,  in[ry][ox]);
                    fma2(*a, wbp, in[ry][ox + 1]);
                    fma2(*a, wc,  in[ry + 1][ox]);
                    fma2(*a, wd,  in[ry + 1][ox + 1]);
                }
        }
        ull bp = ((const ull*)sb2p)[c];
        float blo, bhi; unpk(bp, blo, bhi);
        #pragma unroll
        for (int px = 0; px < 2; px++) {
            float l0, h0, l1, h1, l2, h2, l3, h3;
            unpk(acc[0 * 4 + 2 * px],     l0, h0);
            unpk(acc[0 * 4 + 2 * px + 1], l1, h1);
            unpk(acc[1 * 4 + 2 * px],     l2, h2);
            unpk(acc[1 * 4 + 2 * px + 1], l3, h3);
            float mlo = fmaxf(fmaxf(l0, l1), fmaxf(l2, l3));
            float mhi = fmaxf(fmaxf(h0, h1), fmaxf(h2, h3));
            float vlo = fmaxf(mlo + blo, 0.f);
            float vhi = fmaxf(mhi + bhi, 0.f);
            p2f2[c * 4 + h * 2 + px]        = make_float2(vlo, vlo);
            p2f2[(c + 16) * 4 + h * 2 + px] = make_float2(vhi, vhi);
        }
    }
    __syncwarp();

    // -------- conv3 (32->64, out 3x3) + relu -> feats; SCATTER from 4 real pixels.
    {
        ull a[9];
        #pragma unroll
        for (int i = 0; i < 9; i++) a[i] = 0ULL;
        #pragma unroll 4
        for (int ic = 0; ic < 32; ic++) {
            ulonglong2 v01 = ld2(p2du + ic * 4);
            ulonglong2 v23 = ld2(p2du + ic * 4 + 2);
            ull v00 = v01.x, v0b = v01.y, v10 = v23.x, v11 = v23.y;
            const ull* wb = w3u + (ic * 32 + lane) * 4;             // even offset
            ulonglong2 wt0 = ld2(wb);
            ulonglong2 wt1 = ld2(wb + 2);
            ull w00 = wt0.x, w01 = wt0.y, w10 = wt1.x, w11 = wt1.y;
            fma2(a[0], w11, v00); fma2(a[1], w10, v00);
            fma2(a[3], w01, v00); fma2(a[4], w00, v00);
            fma2(a[1], w11, v0b); fma2(a[2], w10, v0b);
            fma2(a[4], w01, v0b); fma2(a[5], w00, v0b);
            fma2(a[3], w11, v10); fma2(a[4], w10, v10);
            fma2(a[6], w01, v10); fma2(a[7], w00, v10);
            fma2(a[4], w11, v11); fma2(a[5], w10, v11);
            fma2(a[7], w01, v11); fma2(a[8], w00, v11);
        }
        float* fbase = g_feats + (size_t)sf * FEAT_K;
        float b0 = sb3[lane], b1v = sb3[lane + 32];
        #pragma unroll
        for (int p = 0; p < 9; p++) {
            float lo, hi; unpk(a[p], lo, hi);
            fbase[lane * 9 + p]        = fmaxf(lo + b0, 0.f);
            fbase[(lane + 32) * 9 + p] = fmaxf(hi + b1v, 0.f);
        }
        if (lane == 0) {
            fbase[576] = (float)ccol[sf];
            fbase[577] = (float)cobj[sf];
        }
        if (lane < 14) fbase[578 + lane] = 0.f;
    }
}

// ---------------- kernel: proj GEMM  emb[2B,64] = relu(feats * Wt + b), packed ----------------
// block: 256 m x 64 n, 256 threads, thread tile 8m x 8n (4 n-pairs)
__global__ void __launch_bounds__(256) proj_kernel(const float* __restrict__ projb)
{
    __shared__ float As[16][260];      // [k][m]; row = 1040B (16B aligned)
    __shared__ ull   Bsu[16 * 32];     // [k][slot]; slot(np) = (np&3)*8 + (np>>2)
    int tid = threadIdx.x;
    int m0 = blockIdx.x * 256;
    int tx = tid & 7, ty = tid >> 3;   // tx: n-group (8n), ty: 0..31 (8m)
    ull acc[8][4];
    #pragma unroll
    for (int i = 0; i < 8; i++)
        #pragma unroll
        for (int j = 0; j < 4; j++) acc[i][j] = 0ULL;

    for (int k0 = 0; k0 < FEAT_K; k0 += 16) {
        {   // stage A: thread tid owns row m=tid, 16 consecutive k
            const float* src = g_feats + (size_t)(m0 + tid) * FEAT_K + k0;
            #pragma unroll
            for (int q = 0; q < 4; q++) {
                float4 v = *reinterpret_cast<const float4*>(src + q * 4);
                As[q * 4 + 0][tid] = v.x; As[q * 4 + 1][tid] = v.y;
                As[q * 4 + 2][tid] = v.z; As[q * 4 + 3][tid] = v.w;
            }
        }
        {   // stage B with conflict-free slot remap
            int k = tid >> 4, q = tid & 15;
            float4 bv = *reinterpret_cast<const float4*>(g_projwt + (k0 + k) * 64 + q * 4);
            int np0 = 2 * q, np1 = 2 * q + 1;
            int s0 = (np0 & 3) * 8 + (np0 >> 2);
            int s1 = (np1 & 3) * 8 + (np1 >> 2);
            float2* bf2 = (float2*)Bsu;
            bf2[k * 32 + s0] = make_float2(bv.x, bv.y);
            bf2[k * 32 + s1] = make_float2(bv.z, bv.w);
        }
        __syncthreads();
        #pragma unroll
        for (int k = 0; k < 16; k++) {
            ull bp[4];
            #pragma unroll
            for (int j = 0; j < 4; j++) bp[j] = Bsu[k * 32 + j * 8 + tx];   // np = tx*4+j
            float4 alo = *reinterpret_cast<const float4*>(&As[k][ty * 8]);
            float4 ahi = *reinterpret_cast<const float4*>(&As[k][ty * 8 + 4]);
            float a[8] = {alo.x, alo.y, alo.z, alo.w, ahi.x, ahi.y, ahi.z, ahi.w};
            #pragma unroll
            for (int i = 0; i < 8; i++) {
                ull ad = pk_dup(a[i]);
                #pragma unroll
                for (int j = 0; j < 4; j++) fma2(acc[i][j], ad, bp[j]);
            }
        }
        __syncthreads();
    }
    #pragma unroll
    for (int i = 0; i < 8; i++) {
        int m = m0 + ty * 8 + i;
        #pragma unroll
        for (int j = 0; j < 4; j++) {
            int n = tx * 8 + 2 * j;
            float lo, hi; unpk(acc[i][j], lo, hi);
            g_emb[(size_t)m * 64 + n]     = fmaxf(lo + projb[n], 0.f);
            g_emb[(size_t)m * 64 + n + 1] = fmaxf(hi + projb[n + 1], 0.f);
        }
    }
}

// ---------------- kernel: fused comb + MLP (h1 -> LN -> relu -> h2 -> relu -> h3), packed ----------------
// smem floats: As[136*129] (comb -> Hs -> h2T overlay) + Bs[68*128] (half-K weight staging) + sh3[128*8]
#define MLP_AS (136 * 129)
#define MLP_BS (68 * 128)
#define MLP_SH3 (128 * 8)
#define MLP_SMEM_FLOATS (MLP_AS + MLP_BS + MLP_SH3)

__global__ void __launch_bounds__(256, 2) mlp_kernel(
    const float* __restrict__ h1b, const float* __restrict__ lng, const float* __restrict__ lnb,
    const float* __restrict__ h2b, const float* __restrict__ h3w, const float* __restrict__ h3b,
    float* __restrict__ out)
{
    extern __shared__ float smem[];
    float* As   = smem;                 // comb^T [k][m] stride 129; later Hs, later h2^T
    float* Bsf  = As + MLP_AS;          // weight staging [k-half][slot]
    float* sh3f = Bsf + MLP_BS;         // h3 transposed [k][8] (j<7 real)
    ull* Bsu  = (ull*)Bsf;
    ull* sh3u = (ull*)sh3f;

    int tid = threadIdx.x;
    int m0 = blockIdx.x * 128;
    int tx = tid & 15, ty = tid >> 4;

    auto load_bs_half = [&](const float* wsrc, int rows) {
        for (int i = tid; i < rows * 32; i += 256) {
            int k = i >> 5, q = i & 31;
            float4 bv = *reinterpret_cast<const float4*>(wsrc + k * 128 + q * 4);
            int np0 = 2 * q, np1 = 2 * q + 1;
            int s0 = (np0 & 3) * 16 + (np0 >> 2);
            int s1 = (np1 & 3) * 16 + (np1 >> 2);
            float2* bf2 = (float2*)Bsu;
            bf2[k * 64 + s0] = make_float2(bv.x, bv.y);
            bf2[k * 64 + s1] = make_float2(bv.z, bv.w);
        }
    };

    // ---- build comb directly into As; stage sh3; stage h1 weights half 0
    for (int i = tid; i < 128 * COMB_K; i += 256) {
        int m = i / COMB_K, k = i - m * COMB_K;
        int b = m0 + m;
        float v;
        if (k < 64)       v = g_emb[(size_t)b * 64 + k];
        else if (k < 128) v = g_emb[(size_t)(NB + b) * 64 + (k - 64)];
        else if (k < 130) {
            int delta = ((g_dir[NB + b] - g_dir[b]) + 4) & 3;
            float ang = (float)delta * (2.0f * 3.14159f / 4.0f);
            v = (k == 128) ? sinf(ang) : cosf(ang);
        }
        else if (k == 130) v = g_pos[(NB + b) * 2 + 0] - g_pos[b * 2 + 0];
        else if (k == 131) v = g_pos[(NB + b) * 2 + 1] - g_pos[b * 2 + 1];
        else v = 0.f;
        As[k * 129 + m] = v;
    }
    for (int i = tid; i < 128 * 8; i += 256) {
        int k = i >> 3, j = i & 7;
        sh3f[i] = (j < 7) ? h3w[j * 128 + k] : 0.f;
    }
    load_bs_half(g_h1wt, 68);
    __syncthreads();

    // ---- GEMM1: h[128m][128n] = comb * h1wt  (half-K staged, k unrolled x2)
    ull acc[8][4];
    #pragma unroll
    for (int i = 0; i < 8; i++)
        #pragma unroll
        for (int j = 0; j < 4; j++) acc[i][j] = 0ULL;
    #pragma unroll 1
    for (int half = 0; half < 2; half++) {
        if (half) {
            __syncthreads();
            load_bs_half(g_h1wt + 68 * 128, 68);
            __syncthreads();
        }
        int kb = half * 68;
        for (int k = 0; k < 68; k += 2) {
            ull bp0[4], bp1[4];
            float a0[8], a1[8];
            #pragma unroll
            for (int j = 0; j < 4; j++) {
                bp0[j] = Bsu[k * 64 + j * 16 + tx];
                bp1[j] = Bsu[(k + 1) * 64 + j * 16 + tx];
            }
            #pragma unroll
            for (int i = 0; i < 8; i++) {
                a0[i] = As[(kb + k) * 129 + ty * 8 + i];
                a1[i] = As[(kb + k + 1) * 129 + ty * 8 + i];
            }
            #pragma unroll
            for (int i = 0; i < 8; i++) {
                ull ad = pk_dup(a0[i]);
                #pragma unroll
                for (int j = 0; j < 4; j++) fma2(acc[i][j], ad, bp0[j]);
            }
            #pragma unroll
            for (int i = 0; i < 8; i++) {
                ull ad = pk_dup(a1[i]);
                #pragma unroll
                for (int j = 0; j < 4; j++) fma2(acc[i][j], ad, bp1[j]);
            }
        }
    }
    __syncthreads();   // all reads of As (comb) done

    // ---- write pre-LN h (+bias) transposed into As region (Hs[feature][m]); stage h2 half 0
    float* Hs = As;
    #pragma unroll
    for (int j = 0; j < 4; j++) {
        int n = tx * 8 + 2 * j;
        float bn0 = h1b[n], bn1 = h1b[n + 1];
        #pragma unroll
        for (int i = 0; i < 8; i++) {
            int m = ty * 8 + i;
            float lo, hi; unpk(acc[i][j], lo, hi);
            Hs[n * 129 + m]       = lo + bn0;
            Hs[(n + 1) * 129 + m] = hi + bn1;
        }
    }
    load_bs_half(g_h2wt, 64);
    __syncthreads();

    // ---- LayerNorm + relu: 2 threads per sample row
    {
        int m = tid >> 1, halfr = tid & 1;
        int kb = halfr * 64;
        float s = 0.f, s2 = 0.f;
        for (int k = kb; k < kb + 64; k++) {
            float v = Hs[k * 129 + m];
            s += v; s2 += v * v;
        }
        s  += __shfl_xor_sync(0xffffffffu, s, 1);
        s2 += __shfl_xor_sync(0xffffffffu, s2, 1);
        float mu = s * (1.f / 128.f);
        float var = s2 * (1.f / 128.f) - mu * mu;
        float rs = rsqrtf(var + 1e-5f);
        for (int k = kb; k < kb + 64; k++) {
            float v = Hs[k * 129 + m];
            Hs[k * 129 + m] = fmaxf((v - mu) * rs * lng[k] + lnb[k], 0.f);
        }
    }
    __syncthreads();

    // ---- GEMM2: h2 = relu(h * h2wt + b)  (half-K staged, k unrolled x2)
    ull acc2[8][4];
    #pragma unroll
    for (int i = 0; i < 8; i++)
        #pragma unroll
        for (int j = 0; j < 4; j++) acc2[i][j] = 0ULL;
    #pragma unroll 1
    for (int half = 0; half < 2; half++) {
        if (half) {
            __syncthreads();
            load_bs_half(g_h2wt + 64 * 128, 64);
            __syncthreads();
        }
        int kb = half * 64;
        for (int k = 0; k < 64; k += 2) {
            ull bp0[4], bp1[4];
            float a0[8], a1[8];
            #pragma unroll
            for (int j = 0; j < 4; j++) {
                bp0[j] = Bsu[k * 64 + j * 16 + tx];
                bp1[j] = Bsu[(k + 1) * 64 + j * 16 + tx];
            }
            #pragma unroll
            for (int i = 0; i < 8; i++) {
                a0[i] = Hs[(kb + k) * 129 + ty * 8 + i];
                a1[i] = Hs[(kb + k + 1) * 129 + ty * 8 + i];
            }
            #pragma unroll
            for (int i = 0; i < 8; i++) {
                ull ad = pk_dup(a0[i]);
                #pragma unroll
                for (int j = 0; j < 4; j++) fma2(acc2[i][j], ad, bp0[j]);
            }
            #pragma unroll
            for (int i = 0; i < 8; i++) {
                ull ad = pk_dup(a1[i]);
                #pragma unroll
                for (int j = 0; j < 4; j++) fma2(acc2[i][j], ad, bp1[j]);
            }
        }
    }
    __syncthreads();   // all reads of Hs done

    // ---- write h2 (relu) transposed into As region again
    #pragma unroll
    for (int j = 0; j < 4; j++) {
        int n = tx * 8 + 2 * j;
        float bn0 = h2b[n], bn1 = h2b[n + 1];
        #pragma unroll
        for (int i = 0; i < 8; i++) {
            int m = ty * 8 + i;
            float lo, hi; unpk(acc2[i][j], lo, hi);
            As[n * 129 + m]       = fmaxf(lo + bn0, 0.f);
            As[(n + 1) * 129 + m] = fmaxf(hi + bn1, 0.f);
        }
    }
    __syncthreads();

    // ---- h3: out[m][7]  (packed j-pairs via transposed sh3)
    if (tid < 128) {
        int m = tid;
        ull acc3[4];
        #pragma unroll
        for (int j = 0; j < 4; j++) acc3[j] = 0ULL;
        for (int k = 0; k < 128; k++) {
            ull ad = pk_dup(As[k * 129 + m]);
            #pragma unroll
            for (int j = 0; j < 4; j++) fma2(acc3[j], ad, sh3u[k * 4 + j]);
        }
        float r[8];
        #pragma unroll
        for (int j = 0; j < 4; j++) unpk(acc3[j], r[2 * j], r[2 * j + 1]);
        #pragma unroll
        for (int j = 0; j < 7; j++)
            out[(size_t)(m0 + m) * 7 + j] = r[j] + h3b[j];
    }
}

// ---------------- launch ----------------
extern "C" void kernel_launch(void* const* d_in, const int* in_sizes, int n_in,
                              void* d_out, int out_size)
{
    const int*   frame = (const int*)d_in[0];
    const int*   ccol  = (const int*)d_in[1];
    const int*   cobj  = (const int*)d_in[2];
    const float* c1w = (const float*)d_in[3];
    const float* c1b = (const float*)d_in[4];
    const float* c2w = (const float*)d_in[5];
    const float* c2b = (const float*)d_in[6];
    const float* c3w = (const float*)d_in[7];
    const float* c3b = (const float*)d_in[8];
    const float* pw  = (const float*)d_in[9];
    const float* pb  = (const float*)d_in[10];
    const float* h1w = (const float*)d_in[11];
    const float* h1b = (const float*)d_in[12];
    const float* lng = (const float*)d_in[13];
    const float* lnb = (const float*)d_in[14];
    const float* h2w = (const float*)d_in[15];
    const float* h2b = (const float*)d_in[16];
    const float* h3w = (const float*)d_in[17];
    const float* h3b = (const float*)d_in[18];
    float* out = (float*)d_out;

    cudaFuncSetAttribute(encode_kernel, cudaFuncAttributeMaxDynamicSharedMemorySize,
                         ENC_SMEM_FLOATS * (int)sizeof(float));
    cudaFuncSetAttribute(mlp_kernel, cudaFuncAttributeMaxDynamicSharedMemorySize,
                         MLP_SMEM_FLOATS * (int)sizeof(float));

    {
        int total = FEAT_K * 64 + COMB_K * 128 + 128 * 128;
        prep_kernel<<<(total + 255) / 256, 256>>>(pw, h1w, h2w);
    }
    encode_kernel<<<NSF / ENC_WARPS, ENC_THREADS,
                    ENC_SMEM_FLOATS * sizeof(float)>>>(
        frame, ccol, cobj, c1w, c1b, c2w, c2b, c3w, c3b);
    proj_kernel<<<NSF / 256, 256>>>(pb);
    mlp_kernel<<<NB / 128, 256, MLP_SMEM_FLOATS * sizeof(float)>>>(
        h1b, lng, lnb, h2b, h3w, h3b, out);
}

// round 13
// speedup vs baseline: 1.6428x; 1.1066x over previous
#include <cuda_runtime.h>
#include <cuda_bf16.h>
#include <math.h>

// ---------------- problem constants ----------------
#define NB 32768            // batch
#define NSF (2*NB)          // sample-frames
#define FEAT_K 608          // 578 padded to 32 (19 x 32); layout: [p][ch] p-major (k = p*64+ch, k<576)
#define COMB_K 136          // 132 padded to 8

typedef unsigned long long ull;

// ---------------- packed fp32x2 helpers (Blackwell FFMA2) ----------------
__device__ __forceinline__ ull pk_dup(float x) {
    ull r; unsigned u = __float_as_uint(x);
    asm("mov.b64 %0, {%1, %1};" : "=l"(r) : "r"(u));
    return r;
}
__device__ __forceinline__ void fma2(ull& d, ull a, ull b) {
    asm("fma.rn.f32x2 %0, %1, %2, %3;" : "=l"(d) : "l"(a), "l"(b), "l"(d));
}
__device__ __forceinline__ void unpk(ull v, float& lo, float& hi) {
    unsigned a, b;
    asm("mov.b64 {%0, %1}, %2;" : "=r"(a), "=r"(b) : "l"(v));
    lo = __uint_as_float(a); hi = __uint_as_float(b);
}
__device__ __forceinline__ ulonglong2 ld2(const ull* p) {   // p must be 16B aligned
    return *reinterpret_cast<const ulonglong2*>(p);
}

// ---------------- device scratch (static, no allocs) ----------------
__device__ float g_feats[(size_t)NSF * FEAT_K];   // ~159 MB, [sf][p*64+ch] layout
__device__ float g_emb[(size_t)NSF * 64];
__device__ int   g_dir[NSF];
__device__ float g_pos[NSF * 2];
__device__ float g_projwt[FEAT_K * 64];           // [k_new][e]; k_new = p*64+ch
__device__ float g_h1wt[COMB_K * 128];            // [k][o], zero-padded k>=132
__device__ float g_h2wt[128 * 128];               // [k][o]

// ---------------- kernel: weight transposes ----------------
__global__ void prep_kernel(const float* __restrict__ projw,
                            const float* __restrict__ h1w,
                            const float* __restrict__ h2w) {
    int i = blockIdx.x * 256 + threadIdx.x;
    const int N1 = FEAT_K * 64;
    const int N2 = COMB_K * 128;
    const int N3 = 128 * 128;
    if (i < N1) {
        int k = i / 64, e = i % 64;
        float v = 0.f;
        if (k < 576) {
            int p = k / 64, ch = k % 64;
            v = projw[e * 578 + (ch * 9 + p)];
        } else if (k < 578) {
            v = projw[e * 578 + k];
        }
        g_projwt[i] = v;
    } else if (i < N1 + N2) {
        int j = i - N1;
        int k = j / 128, o = j % 128;
        g_h1wt[j] = (k < 132) ? h1w[o * 132 + k] : 0.f;
    } else if (i < N1 + N2 + N3) {
        int j = i - N1 - N2;
        int k = j / 128, o = j % 128;
        g_h2wt[j] = h2w[o * 128 + k];
    }
}

// ---------------- kernel: conv encoder (warp per sample-frame, packed f32x2, LDS.128) ----------------
// smem floats:
//  sw1p[192] sb1p[16] sw2p[2048] sb2p[32] sw3p[8192] sb3[64] = 10544  (all pair layouts, .128-friendly)
//  per warp (16): xind[540]([3][9][10] pairs, dup) p1d[1152]([16][6][6] pairs) p2d[256]([32][2][2] pairs) = 1948
#define ENC_WARPS 16
#define ENC_THREADS (ENC_WARPS * 32)
#define ENC_WEIGHTS 10544
#define ENC_PERWARP 1948
#define ENC_SMEM_FLOATS (ENC_WEIGHTS + ENC_WARPS * ENC_PERWARP)

__global__ void __launch_bounds__(ENC_THREADS, 1) encode_kernel(
    const int* __restrict__ frame, const int* __restrict__ ccol, const int* __restrict__ cobj,
    const float* __restrict__ w1g, const float* __restrict__ b1g,
    const float* __restrict__ w2g, const float* __restrict__ b2g,
    const float* __restrict__ w3g, const float* __restrict__ b3g)
{
    extern __shared__ float smem[];
    float* sw1p = smem;                 // pairs: cp*12 + r        (r = ic*4+t; sel: +0 ch cp, +1 ch cp+8)
    float* sb1p = sw1p + 192;           // pairs: cp
    float* sw2p = sb1p + 16;            // pairs: (ic*16+c)*4 + t  (sel: +0 ch c, +1 ch c+16)
    float* sb2p = sw2p + 2048;          // pairs: c
    float* sw3p = sb2p + 32;            // pairs: (ic*32+l)*4 + t  (sel: +0 ch l, +1 ch l+32)
    float* sb3  = sw3p + 8192;
    float* swarp = sb3 + 64;

    int tid = threadIdx.x;
    for (int i = tid; i < 192; i += ENC_THREADS) {
        int c = i / 12, r = i % 12;
        int cp = c & 7, sel = c >> 3;
        sw1p[(cp * 12 + r) * 2 + sel] = w1g[i];
    }
    if (tid < 16) sb1p[(tid & 7) * 2 + (tid >> 3)] = b1g[tid];
    for (int i = tid; i < 2048; i += ENC_THREADS) {
        int oc = i >> 6, rem = i & 63;          // rem = ic*4+t
        int ic = rem >> 2, t = rem & 3;
        int c = oc & 15, sel = oc >> 4;
        sw2p[(((ic * 16 + c) * 4) + t) * 2 + sel] = w2g[i];
    }
    if (tid < 32) sb2p[(tid & 15) * 2 + (tid >> 4)] = b2g[tid];
    for (int i = tid; i < 8192; i += ENC_THREADS) {
        int oc = i >> 7, rem = i & 127;         // rem = ic*4+t
        int ic = rem >> 2, t = rem & 3;
        int l = oc & 31, sel = oc >> 5;
        sw3p[(((ic * 32 + l) * 4) + t) * 2 + sel] = w3g[i];
    }
    if (tid < 64) sb3[tid] = b3g[tid];
    __syncthreads();

    int warp = tid >> 5, lane = tid & 31;
    int sf = blockIdx.x * ENC_WARPS + warp;
    if (sf >= NSF) return;

    float* wbase = swarp + warp * ENC_PERWARP;
    float* xind = wbase;                // [3][9][10] duplicated pairs (540 floats)
    float* p1d  = wbase + 540;          // [16][6][6] duplicated pairs
    float* p2d  = wbase + 1692;         // [32][2][2] duplicated pairs (real only)
    float2* xinf2 = (float2*)xind;
    float2* p1f2 = (float2*)p1d;
    float2* p2f2 = (float2*)p2d;
    const ull* xinu = (const ull*)xind;
    const ull* p1du = (const ull*)p1d;
    const ull* p2du = (const ull*)p2d;
    const ull* w1u = (const ull*)sw1p;
    const ull* b1u = (const ull*)sb1p;
    const ull* w2u = (const ull*)sw2p;
    const ull* w3u = (const ull*)sw3p;

    const int* fb = frame + (size_t)sf * 147;

    // zero xind + p1d as pairs (p2d is fully written by conv2)
    for (int i = lane; i < 846; i += 32) ((float2*)wbase)[i] = make_float2(0.f, 0.f);
    __syncwarp();
    for (int i = lane; i < 147; i += 32) {
        int y = i / 21, r = i % 21, x = r / 3, c = r % 3;
        float v = (float)fb[i];
        xinf2[c * 90 + (y + 1) * 10 + (x + 1)] = make_float2(v, v);
    }
    // dir/pos via ballot (first row-major position where ch0 == 10)
    {
        int v0 = fb[lane * 3];
        unsigned m0 = __ballot_sync(0xffffffffu, v0 == 10);
        int p2i = 32 + lane;
        int v1 = (p2i < 49) ? fb[p2i * 3] : 0;
        unsigned m1 = __ballot_sync(0xffffffffu, (p2i < 49) && (v1 == 10));
        if (lane == 0) {
            int idx = m0 ? (__ffs(m0) - 1) : (m1 ? (31 + __ffs(m1)) : -1);
            int d = 0; float py = 0.5f, px = 0.5f;
            if (idx >= 0) {
                d = fb[idx * 3 + 2] & 3;
                py = (float)(idx / 7) * (1.f / 6.f);
                px = (float)(idx % 7) * (1.f / 6.f);
            }
            g_dir[sf] = d;
            g_pos[sf * 2 + 0] = py;
            g_pos[sf * 2 + 1] = px;
        }
    }
    __syncwarp();

    // -------- conv1 (3->16, k2 pad1, out 8x8) + relu + pool2 -> p1d interior [16][4][4]
    // lane = (cp in 0..7, quad in 0..3); channel pair (cp, cp+8), quadrant of 4x4 conv outputs
    {
        int cp = lane & 7, quad = lane >> 3;
        int qy = quad >> 1, qx = quad & 1;
        ull w[12];
        #pragma unroll
        for (int r2 = 0; r2 < 6; r2++) {
            ulonglong2 t = ld2(w1u + cp * 12 + r2 * 2);
            w[r2 * 2] = t.x; w[r2 * 2 + 1] = t.y;
        }
        float blo, bhi;
        { ull bp = b1u[cp]; unpk(bp, blo, bhi); }
        ull acc[16];
        #pragma unroll
        for (int i = 0; i < 16; i++) acc[i] = 0ULL;
        #pragma unroll
        for (int ic = 0; ic < 3; ic++) {
            const ull* xb = xinu + ic * 90 + (4 * qy) * 10 + 4 * qx;   // even offset
            ull in[5][5];
            #pragma unroll
            for (int r = 0; r < 5; r++) {
                ulonglong2 t0 = ld2(xb + r * 10);
                ulonglong2 t1 = ld2(xb + r * 10 + 2);
                in[r][0] = t0.x; in[r][1] = t0.y;
                in[r][2] = t1.x; in[r][3] = t1.y;
                in[r][4] = xb[r * 10 + 4];
            }
            ull w0 = w[ic * 4 + 0], w1 = w[ic * 4 + 1];
            ull w2 = w[ic * 4 + 2], w3 = w[ic * 4 + 3];
            #pragma unroll
            for (int oy = 0; oy < 4; oy++)
                #pragma unroll
                for (int ox = 0; ox < 4; ox++) {
                    ull* a = &acc[oy * 4 + ox];
                    fma2(*a, w0, in[oy][ox]);
                    fma2(*a, w1, in[oy][ox + 1]);
                    fma2(*a, w2, in[oy + 1][ox]);
                    fma2(*a, w3, in[oy + 1][ox + 1]);
                }
        }
        #pragma unroll
        for (int pr = 0; pr < 2; pr++)
            #pragma unroll
            for (int pc = 0; pc < 2; pc++) {
                float l0, h0, l1, h1, l2, h2, l3, h3;
                unpk(acc[(2 * pr) * 4 + 2 * pc],         l0, h0);
                unpk(acc[(2 * pr) * 4 + 2 * pc + 1],     l1, h1);
                unpk(acc[(2 * pr + 1) * 4 + 2 * pc],     l2, h2);
                unpk(acc[(2 * pr + 1) * 4 + 2 * pc + 1], l3, h3);
                float mlo = fmaxf(fmaxf(l0, l1), fmaxf(l2, l3));
                float mhi = fmaxf(fmaxf(h0, h1), fmaxf(h2, h3));
                float vlo = fmaxf(mlo + blo, 0.f);
                float vhi = fmaxf(mhi + bhi, 0.f);
                int py = 2 * qy + pr, px = 2 * qx + pc;
                p1f2[cp * 36 + (py + 1) * 6 + (px + 1)]       = make_float2(vlo, vlo);
                p1f2[(cp + 8) * 36 + (py + 1) * 6 + (px + 1)] = make_float2(vhi, vhi);
            }
    }
    __syncwarp();

    // -------- conv2 (16->32) + relu + pool -> p2d [32][2][2] (real only)
    // lane = (c in 0..15, h in 0..1); channel pair (c, c+16), conv-output rows {2h, 2h+1}
    {
        int c = lane & 15, h = lane >> 4;
        ull acc[8];
        #pragma unroll
        for (int i = 0; i < 8; i++) acc[i] = 0ULL;
        #pragma unroll 4
        for (int ic = 0; ic < 16; ic++) {
            ull in[3][5];
            #pragma unroll
            for (int r = 0; r < 3; r++) {
                const ull* rb = p1du + ic * 36 + (2 * h + r) * 6;   // even offset
                ulonglong2 t0 = ld2(rb);
                ulonglong2 t1 = ld2(rb + 2);
                in[r][0] = t0.x; in[r][1] = t0.y;
                in[r][2] = t1.x; in[r][3] = t1.y;
                in[r][4] = rb[4];
            }
            const ull* wb = w2u + (ic * 16 + c) * 4;                // even offset
            ulonglong2 wt0 = ld2(wb);
            ulonglong2 wt1 = ld2(wb + 2);
            ull wa = wt0.x, wbp = wt0.y, wc = wt1.x, wd = wt1.y;
            #pragma unroll
            for (int ry = 0; ry < 2; ry++)
                #pragma unroll
                for (int ox = 0; ox < 4; ox++) {
                    ull* a = &acc[ry * 4 + ox];
                    fma2(*a, wa,  in[ry][ox]);
                    fma2(*a, wbp, in[ry][ox + 1]);
                    fma2(*a, wc,  in[ry + 1][ox]);
                    fma2(*a, wd,  in[ry + 1][ox + 1]);
                }
        }
        ull bp = ((const ull*)sb2p)[c];
        float blo, bhi; unpk(bp, blo, bhi);
        #pragma unroll
        for (int px = 0; px < 2; px++) {
            float l0, h0, l1, h1, l2, h2, l3, h3;
            unpk(acc[0 * 4 + 2 * px],     l0, h0);
            unpk(acc[0 * 4 + 2 * px + 1], l1, h1);
            unpk(acc[1 * 4 + 2 * px],     l2, h2);
            unpk(acc[1 * 4 + 2 * px + 1], l3, h3);
            float mlo = fmaxf(fmaxf(l0, l1), fmaxf(l2, l3));
            float mhi = fmaxf(fmaxf(h0, h1), fmaxf(h2, h3));
            float vlo = fmaxf(mlo + blo, 0.f);
            float vhi = fmaxf(mhi + bhi, 0.f);
            p2f2[c * 4 + h * 2 + px]        = make_float2(vlo, vlo);
            p2f2[(c + 16) * 4 + h * 2 + px] = make_float2(vhi, vhi);
        }
    }
    __syncwarp();

    // -------- conv3 (32->64, out 3x3) + relu -> feats; SCATTER from 4 real pixels.
    // feats stored POSITION-MAJOR: g_feats[sf][p*64 + ch] — coalesced stores.
    {
        ull a[9];
        #pragma unroll
        for (int i = 0; i < 9; i++) a[i] = 0ULL;
        #pragma unroll 4
        for (int ic = 0; ic < 32; ic++) {
            ulonglong2 v01 = ld2(p2du + ic * 4);
            ulonglong2 v23 = ld2(p2du + ic * 4 + 2);
            ull v00 = v01.x, v0b = v01.y, v10 = v23.x, v11 = v23.y;
            const ull* wb = w3u + (ic * 32 + lane) * 4;             // even offset
            ulonglong2 wt0 = ld2(wb);
            ulonglong2 wt1 = ld2(wb + 2);
            ull w00 = wt0.x, w01 = wt0.y, w10 = wt1.x, w11 = wt1.y;
            fma2(a[0], w11, v00); fma2(a[1], w10, v00);
            fma2(a[3], w01, v00); fma2(a[4], w00, v00);
            fma2(a[1], w11, v0b); fma2(a[2], w10, v0b);
            fma2(a[4], w01, v0b); fma2(a[5], w00, v0b);
            fma2(a[3], w11, v10); fma2(a[4], w10, v10);
            fma2(a[6], w01, v10); fma2(a[7], w00, v10);
            fma2(a[4], w11, v11); fma2(a[5], w10, v11);
            fma2(a[7], w01, v11); fma2(a[8], w00, v11);
        }
        float* fbase = g_feats + (size_t)sf * FEAT_K;
        float b0 = sb3[lane], b1v = sb3[lane + 32];
        #pragma unroll
        for (int p = 0; p < 9; p++) {
            float lo, hi; unpk(a[p], lo, hi);
            fbase[p * 64 + lane]      = fmaxf(lo + b0, 0.f);
            fbase[p * 64 + 32 + lane] = fmaxf(hi + b1v, 0.f);
        }
        if (lane == 0) {
            fbase[576] = (float)ccol[sf];
            fbase[577] = (float)cobj[sf];
        }
        if (lane < 30) fbase[578 + lane] = 0.f;
    }
}

// ---------------- kernel: proj GEMM  emb[2B,64] = relu(feats * Wt + b), packed ----------------
// block: 256 m x 64 n, 256 threads, thread tile 8m x 8n (4 n-pairs); k-step 32, coalesced A staging
__global__ void __launch_bounds__(256) proj_kernel(const float* __restrict__ projb)
{
    __shared__ float As[32][260];      // [k][m]; row = 1040B
    __shared__ ull   Bsu[32 * 32];     // [k][slot]; slot(np) = (np&3)*8 + (np>>2)
    int tid = threadIdx.x;
    int m0 = blockIdx.x * 256;
    int tx = tid & 7, ty = tid >> 3;   // tx: n-group (8n), ty: 0..31 (8m)
    ull acc[8][4];
    #pragma unroll
    for (int i = 0; i < 8; i++)
        #pragma unroll
        for (int j = 0; j < 4; j++) acc[i][j] = 0ULL;

    for (int k0 = 0; k0 < FEAT_K; k0 += 32) {
        {   // stage A coalesced: 8 threads cover one row's 128B segment; 8 reps cover 256 rows
            int q = tid & 7, rbase = tid >> 3;
            #pragma unroll
            for (int rep = 0; rep < 8; rep++) {
                int row = rep * 32 + rbase;
                float4 v = *reinterpret_cast<const float4*>(
                    g_feats + (size_t)(m0 + row) * FEAT_K + k0 + q * 4);
                As[q * 4 + 0][row] = v.x; As[q * 4 + 1][row] = v.y;
                As[q * 4 + 2][row] = v.z; As[q * 4 + 3][row] = v.w;
            }
        }
        {   // stage B with conflict-free slot remap: 32 k x 64 n = 512 float4, 2 per thread
            #pragma unroll
            for (int rep = 0; rep < 2; rep++) {
                int idx = rep * 256 + tid;
                int k = idx >> 4, q = idx & 15;
                float4 bv = *reinterpret_cast<const float4*>(g_projwt + (k0 + k) * 64 + q * 4);
                int np0 = 2 * q, np1 = 2 * q + 1;
                int s0 = (np0 & 3) * 8 + (np0 >> 2);
                int s1 = (np1 & 3) * 8 + (np1 >> 2);
                float2* bf2 = (float2*)Bsu;
                bf2[k * 32 + s0] = make_float2(bv.x, bv.y);
                bf2[k * 32 + s1] = make_float2(bv.z, bv.w);
            }
        }
        __syncthreads();
        #pragma unroll
        for (int k = 0; k < 32; k++) {
            ull bp[4];
            #pragma unroll
            for (int j = 0; j < 4; j++) bp[j] = Bsu[k * 32 + j * 8 + tx];   // np = tx*4+j
            float4 alo = *reinterpret_cast<const float4*>(&As[k][ty * 8]);
            float4 ahi = *reinterpret_cast<const float4*>(&As[k][ty * 8 + 4]);
            float a[8] = {alo.x, alo.y, alo.z, alo.w, ahi.x, ahi.y, ahi.z, ahi.w};
            #pragma unroll
            for (int i = 0; i < 8; i++) {
                ull ad = pk_dup(a[i]);
                #pragma unroll
                for (int j = 0; j < 4; j++) fma2(acc[i][j], ad, bp[j]);
            }
        }
        __syncthreads();
    }
    #pragma unroll
    for (int i = 0; i < 8; i++) {
        int m = m0 + ty * 8 + i;
        #pragma unroll
        for (int j = 0; j < 4; j++) {
            int n = tx * 8 + 2 * j;
            float lo, hi; unpk(acc[i][j], lo, hi);
            g_emb[(size_t)m * 64 + n]     = fmaxf(lo + projb[n], 0.f);
            g_emb[(size_t)m * 64 + n + 1] = fmaxf(hi + projb[n + 1], 0.f);
        }
    }
}

// ---------------- kernel: fused comb + MLP (h1 -> LN -> relu -> h2 -> relu -> h3), packed ----------------
// smem floats: As[136*129] (comb -> Hs -> h2T overlay) + Bs[68*128] (half-K weight staging) + sh3[128*8]
#define MLP_AS (136 * 129)
#define MLP_BS (68 * 128)
#define MLP_SH3 (128 * 8)
#define MLP_SMEM_FLOATS (MLP_AS + MLP_BS + MLP_SH3)

__global__ void __launch_bounds__(256, 2) mlp_kernel(
    const float* __restrict__ h1b, const float* __restrict__ lng, const float* __restrict__ lnb,
    const float* __restrict__ h2b, const float* __restrict__ h3w, const float* __restrict__ h3b,
    float* __restrict__ out)
{
    extern __shared__ float smem[];
    float* As   = smem;                 // comb^T [k][m] stride 129; later Hs, later h2^T
    float* Bsf  = As + MLP_AS;          // weight staging [k-half][slot]
    float* sh3f = Bsf + MLP_BS;         // h3 transposed [k][8] (j<7 real)
    ull* Bsu  = (ull*)Bsf;
    ull* sh3u = (ull*)sh3f;

    int tid = threadIdx.x;
    int m0 = blockIdx.x * 128;
    int tx = tid & 15, ty = tid >> 4;

    auto load_bs_half = [&](const float* wsrc, int rows) {
        for (int i = tid; i < rows * 32; i += 256) {
            int k = i >> 5, q = i & 31;
            float4 bv = *reinterpret_cast<const float4*>(wsrc + k * 128 + q * 4);
            int np0 = 2 * q, np1 = 2 * q + 1;
            int s0 = (np0 & 3) * 16 + (np0 >> 2);
            int s1 = (np1 & 3) * 16 + (np1 >> 2);
            float2* bf2 = (float2*)Bsu;
            bf2[k * 64 + s0] = make_float2(bv.x, bv.y);
            bf2[k * 64 + s1] = make_float2(bv.z, bv.w);
        }
    };

    // ---- build comb directly into As; stage sh3; stage h1 weights half 0
    for (int i = tid; i < 128 * COMB_K; i += 256) {
        int m = i / COMB_K, k = i - m * COMB_K;
        int b = m0 + m;
        float v;
        if (k < 64)       v = g_emb[(size_t)b * 64 + k];
        else if (k < 128) v = g_emb[(size_t)(NB + b) * 64 + (k - 64)];
        else if (k < 130) {
            int delta = ((g_dir[NB + b] - g_dir[b]) + 4) & 3;
            float ang = (float)delta * (2.0f * 3.14159f / 4.0f);
            v = (k == 128) ? sinf(ang) : cosf(ang);
        }
        else if (k == 130) v = g_pos[(NB + b) * 2 + 0] - g_pos[b * 2 + 0];
        else if (k == 131) v = g_pos[(NB + b) * 2 + 1] - g_pos[b * 2 + 1];
        else v = 0.f;
        As[k * 129 + m] = v;
    }
    for (int i = tid; i < 128 * 8; i += 256) {
        int k = i >> 3, j = i & 7;
        sh3f[i] = (j < 7) ? h3w[j * 128 + k] : 0.f;
    }
    load_bs_half(g_h1wt, 68);
    __syncthreads();

    // ---- GEMM1: h[128m][128n] = comb * h1wt  (half-K staged, k unrolled x2)
    ull acc[8][4];
    #pragma unroll
    for (int i = 0; i < 8; i++)
        #pragma unroll
        for (int j = 0; j < 4; j++) acc[i][j] = 0ULL;
    #pragma unroll 1
    for (int half = 0; half < 2; half++) {
        if (half) {
            __syncthreads();
            load_bs_half(g_h1wt + 68 * 128, 68);
            __syncthreads();
        }
        int kb = half * 68;
        for (int k = 0; k < 68; k += 2) {
            ull bp0[4], bp1[4];
            float a0[8], a1[8];
            #pragma unroll
            for (int j = 0; j < 4; j++) {
                bp0[j] = Bsu[k * 64 + j * 16 + tx];
                bp1[j] = Bsu[(k + 1) * 64 + j * 16 + tx];
            }
            #pragma unroll
            for (int i = 0; i < 8; i++) {
                a0[i] = As[(kb + k) * 129 + ty * 8 + i];
                a1[i] = As[(kb + k + 1) * 129 + ty * 8 + i];
            }
            #pragma unroll
            for (int i = 0; i < 8; i++) {
                ull ad = pk_dup(a0[i]);
                #pragma unroll
                for (int j = 0; j < 4; j++) fma2(acc[i][j], ad, bp0[j]);
            }
            #pragma unroll
            for (int i = 0; i < 8; i++) {
                ull ad = pk_dup(a1[i]);
                #pragma unroll
                for (int j = 0; j < 4; j++) fma2(acc[i][j], ad, bp1[j]);
            }
        }
    }
    __syncthreads();   // all reads of As (comb) done

    // ---- write pre-LN h (+bias) transposed into As region (Hs[feature][m]); stage h2 half 0
    float* Hs = As;
    #pragma unroll
    for (int j = 0; j < 4; j++) {
        int n = tx * 8 + 2 * j;
        float bn0 = h1b[n], bn1 = h1b[n + 1];
        #pragma unroll
        for (int i = 0; i < 8; i++) {
            int m = ty * 8 + i;
            float lo, hi; unpk(acc[i][j], lo, hi);
            Hs[n * 129 + m]       = lo + bn0;
            Hs[(n + 1) * 129 + m] = hi + bn1;
        }
    }
    load_bs_half(g_h2wt, 64);
    __syncthreads();

    // ---- LayerNorm + relu: 2 threads per sample row
    {
        int m = tid >> 1, halfr = tid & 1;
        int kb = halfr * 64;
        float s = 0.f, s2 = 0.f;
        for (int k = kb; k < kb + 64; k++) {
            float v = Hs[k * 129 + m];
            s += v; s2 += v * v;
        }
        s  += __shfl_xor_sync(0xffffffffu, s, 1);
        s2 += __shfl_xor_sync(0xffffffffu, s2, 1);
        float mu = s * (1.f / 128.f);
        float var = s2 * (1.f / 128.f) - mu * mu;
        float rs = rsqrtf(var + 1e-5f);
        for (int k = kb; k < kb + 64; k++) {
            float v = Hs[k * 129 + m];
            Hs[k * 129 + m] = fmaxf((v - mu) * rs * lng[k] + lnb[k], 0.f);
        }
    }
    __syncthreads();

    // ---- GEMM2: h2 = relu(h * h2wt + b)  (half-K staged, k unrolled x2)
    ull acc2[8][4];
    #pragma unroll
    for (int i = 0; i < 8; i++)
        #pragma unroll
        for (int j = 0; j < 4; j++) acc2[i][j] = 0ULL;
    #pragma unroll 1
    for (int half = 0; half < 2; half++) {
        if (half) {
            __syncthreads();
            load_bs_half(g_h2wt + 64 * 128, 64);
            __syncthreads();
        }
        int kb = half * 64;
        for (int k = 0; k < 64; k += 2) {
            ull bp0[4], bp1[4];
            float a0[8], a1[8];
            #pragma unroll
            for (int j = 0; j < 4; j++) {
                bp0[j] = Bsu[k * 64 + j * 16 + tx];
                bp1[j] = Bsu[(k + 1) * 64 + j * 16 + tx];
            }
            #pragma unroll
            for (int i = 0; i < 8; i++) {
                a0[i] = Hs[(kb + k) * 129 + ty * 8 + i];
                a1[i] = Hs[(kb + k + 1) * 129 + ty * 8 + i];
            }
            #pragma unroll
            for (int i = 0; i < 8; i++) {
                ull ad = pk_dup(a0[i]);
                #pragma unroll
                for (int j = 0; j < 4; j++) fma2(acc2[i][j], ad, bp0[j]);
            }
            #pragma unroll
            for (int i = 0; i < 8; i++) {
                ull ad = pk_dup(a1[i]);
                #pragma unroll
                for (int j = 0; j < 4; j++) fma2(acc2[i][j], ad, bp1[j]);
            }
        }
    }
    __syncthreads();   // all reads of Hs done

    // ---- write h2 (relu) transposed into As region again
    #pragma unroll
    for (int j = 0; j < 4; j++) {
        int n = tx * 8 + 2 * j;
        float bn0 = h2b[n], bn1 = h2b[n + 1];
        #pragma unroll
        for (int i = 0; i < 8; i++) {
            int m = ty * 8 + i;
            float lo, hi; unpk(acc2[i][j], lo, hi);
            As[n * 129 + m]       = fmaxf(lo + bn0, 0.f);
            As[(n + 1) * 129 + m] = fmaxf(hi + bn1, 0.f);
        }
    }
    __syncthreads();

    // ---- h3: out[m][7]  (packed j-pairs via transposed sh3)
    if (tid < 128) {
        int m = tid;
        ull acc3[4];
        #pragma unroll
        for (int j = 0; j < 4; j++) acc3[j] = 0ULL;
        for (int k = 0; k < 128; k++) {
            ull ad = pk_dup(As[k * 129 + m]);
            #pragma unroll
            for (int j = 0; j < 4; j++) fma2(acc3[j], ad, sh3u[k * 4 + j]);
        }
        float r[8];
        #pragma unroll
        for (int j = 0; j < 4; j++) unpk(acc3[j], r[2 * j], r[2 * j + 1]);
        #pragma unroll
        for (int j = 0; j < 7; j++)
            out[(size_t)(m0 + m) * 7 + j] = r[j] + h3b[j];
    }
}

// ---------------- launch ----------------
extern "C" void kernel_launch(void* const* d_in, const int* in_sizes, int n_in,
                              void* d_out, int out_size)
{
    const int*   frame = (const int*)d_in[0];
    const int*   ccol  = (const int*)d_in[1];
    const int*   cobj  = (const int*)d_in[2];
    const float* c1w = (const float*)d_in[3];
    const float* c1b = (const float*)d_in[4];
    const float* c2w = (const float*)d_in[5];
    const float* c2b = (const float*)d_in[6];
    const float* c3w = (const float*)d_in[7];
    const float* c3b = (const float*)d_in[8];
    const float* pw  = (const float*)d_in[9];
    const float* pb  = (const float*)d_in[10];
    const float* h1w = (const float*)d_in[11];
    const float* h1b = (const float*)d_in[12];
    const float* lng = (const float*)d_in[13];
    const float* lnb = (const float*)d_in[14];
    const float* h2w = (const float*)d_in[15];
    const float* h2b = (const float*)d_in[16];
    const float* h3w = (const float*)d_in[17];
    const float* h3b = (const float*)d_in[18];
    float* out = (float*)d_out;

    cudaFuncSetAttribute(encode_kernel, cudaFuncAttributeMaxDynamicSharedMemorySize,
                         ENC_SMEM_FLOATS * (int)sizeof(float));
    cudaFuncSetAttribute(mlp_kernel, cudaFuncAttributeMaxDynamicSharedMemorySize,
                         MLP_SMEM_FLOATS * (int)sizeof(float));

    {
        int total = FEAT_K * 64 + COMB_K * 128 + 128 * 128;
        prep_kernel<<<(total + 255) / 256, 256>>>(pw, h1w, h2w);
    }
    encode_kernel<<<NSF / ENC_WARPS, ENC_THREADS,
                    ENC_SMEM_FLOATS * sizeof(float)>>>(
        frame, ccol, cobj, c1w, c1b, c2w, c2b, c3w, c3b);
    proj_kernel<<<NSF / 256, 256>>>(pb);
    mlp_kernel<<<NB / 128, 256, MLP_SMEM_FLOATS * sizeof(float)>>>(
        h1b, lng, lnb, h2b, h3w, h3b, out);
}

// round 15
// speedup vs baseline: 1.6873x; 1.0271x over previous
#include <cuda_runtime.h>
#include <cuda_bf16.h>
#include <math.h>

// ---------------- problem constants ----------------
#define NB 32768            // batch
#define NSF (2*NB)          // sample-frames
#define FEAT_K 608          // 578 padded to 32 (19 x 32); layout: [p][ch] p-major (k = p*64+ch, k<576)
#define COMB_K 136          // 132 padded to 8

typedef unsigned long long ull;

// ---------------- packed fp32x2 helpers (Blackwell FFMA2) ----------------
__device__ __forceinline__ ull pk_dup(float x) {
    ull r; unsigned u = __float_as_uint(x);
    asm("mov.b64 %0, {%1, %1};" : "=l"(r) : "r"(u));
    return r;
}
__device__ __forceinline__ void fma2(ull& d, ull a, ull b) {
    asm("fma.rn.f32x2 %0, %1, %2, %3;" : "=l"(d) : "l"(a), "l"(b), "l"(d));
}
__device__ __forceinline__ void unpk(ull v, float& lo, float& hi) {
    unsigned a, b;
    asm("mov.b64 {%0, %1}, %2;" : "=r"(a), "=r"(b) : "l"(v));
    lo = __uint_as_float(a); hi = __uint_as_float(b);
}
__device__ __forceinline__ ulonglong2 ld2(const ull* p) {   // p must be 16B aligned
    return *reinterpret_cast<const ulonglong2*>(p);
}

// ---------------- device scratch (static, no allocs) ----------------
__device__ float g_feats[(size_t)NSF * FEAT_K];   // ~159 MB, [sf][p*64+ch] layout
__device__ float g_emb[(size_t)NSF * 64];
__device__ int   g_dir[NSF];
__device__ float g_pos[NSF * 2];
__device__ float g_projwt[FEAT_K * 64];           // [k_new][e]; k_new = p*64+ch
__device__ float g_h1wt[COMB_K * 128];            // [k][o], zero-padded k>=132
__device__ float g_h2wt[128 * 128];               // [k][o]

// ---------------- kernel: weight transposes ----------------
__global__ void prep_kernel(const float* __restrict__ projw,
                            const float* __restrict__ h1w,
                            const float* __restrict__ h2w) {
    int i = blockIdx.x * 256 + threadIdx.x;
    const int N1 = FEAT_K * 64;
    const int N2 = COMB_K * 128;
    const int N3 = 128 * 128;
    if (i < N1) {
        int k = i / 64, e = i % 64;
        float v = 0.f;
        if (k < 576) {
            int p = k / 64, ch = k % 64;
            v = projw[e * 578 + (ch * 9 + p)];
        } else if (k < 578) {
            v = projw[e * 578 + k];
        }
        g_projwt[i] = v;
    } else if (i < N1 + N2) {
        int j = i - N1;
        int k = j / 128, o = j % 128;
        g_h1wt[j] = (k < 132) ? h1w[o * 132 + k] : 0.f;
    } else if (i < N1 + N2 + N3) {
        int j = i - N1 - N2;
        int k = j / 128, o = j % 128;
        g_h2wt[j] = h2w[o * 128 + k];
    }
}

// ---------------- kernel: conv encoder (warp per sample-frame, packed f32x2, LDS.128) ----------------
// smem floats:
//  sw1p[192] sb1p[16] sw2p[2048] sb2p[32] sw3p[8192] sb3[64] = 10544  (all pair layouts, .128-friendly)
//  per warp (22): xind[540]([3][9][10] pairs, dup) p1d[1152]([16][6][6] pairs) p2d[256]([32][2][2] pairs) = 1948
// total = 10544 + 22*1948 = 53400 floats = 213.6 KB (1 block/SM, 22 warps resident)
#define ENC_WARPS 22
#define ENC_THREADS (ENC_WARPS * 32)
#define ENC_WEIGHTS 10544
#define ENC_PERWARP 1948
#define ENC_SMEM_FLOATS (ENC_WEIGHTS + ENC_WARPS * ENC_PERWARP)

__global__ void __launch_bounds__(ENC_THREADS, 1) encode_kernel(
    const int* __restrict__ frame, const int* __restrict__ ccol, const int* __restrict__ cobj,
    const float* __restrict__ w1g, const float* __restrict__ b1g,
    const float* __restrict__ w2g, const float* __restrict__ b2g,
    const float* __restrict__ w3g, const float* __restrict__ b3g)
{
    extern __shared__ float smem[];
    float* sw1p = smem;                 // pairs: cp*12 + r        (r = ic*4+t; sel: +0 ch cp, +1 ch cp+8)
    float* sb1p = sw1p + 192;           // pairs: cp
    float* sw2p = sb1p + 16;            // pairs: (ic*16+c)*4 + t  (sel: +0 ch c, +1 ch c+16)
    float* sb2p = sw2p + 2048;          // pairs: c
    float* sw3p = sb2p + 32;            // pairs: (ic*32+l)*4 + t  (sel: +0 ch l, +1 ch l+32)
    float* sb3  = sw3p + 8192;
    float* swarp = sb3 + 64;

    int tid = threadIdx.x;
    for (int i = tid; i < 192; i += ENC_THREADS) {
        int c = i / 12, r = i % 12;
        int cp = c & 7, sel = c >> 3;
        sw1p[(cp * 12 + r) * 2 + sel] = w1g[i];
    }
    if (tid < 16) sb1p[(tid & 7) * 2 + (tid >> 3)] = b1g[tid];
    for (int i = tid; i < 2048; i += ENC_THREADS) {
        int oc = i >> 6, rem = i & 63;          // rem = ic*4+t
        int ic = rem >> 2, t = rem & 3;
        int c = oc & 15, sel = oc >> 4;
        sw2p[(((ic * 16 + c) * 4) + t) * 2 + sel] = w2g[i];
    }
    if (tid < 32) sb2p[(tid & 15) * 2 + (tid >> 4)] = b2g[tid];
    for (int i = tid; i < 8192; i += ENC_THREADS) {
        int oc = i >> 7, rem = i & 127;         // rem = ic*4+t
        int ic = rem >> 2, t = rem & 3;
        int l = oc & 31, sel = oc >> 5;
        sw3p[(((ic * 32 + l) * 4) + t) * 2 + sel] = w3g[i];
    }
    if (tid < 64) sb3[tid] = b3g[tid];
    __syncthreads();

    int warp = tid >> 5, lane = tid & 31;
    int sf = blockIdx.x * ENC_WARPS + warp;
    if (sf >= NSF) return;

    float* wbase = swarp + warp * ENC_PERWARP;
    float* xind = wbase;                // [3][9][10] duplicated pairs (540 floats)
    float* p1d  = wbase + 540;          // [16][6][6] duplicated pairs
    float* p2d  = wbase + 1692;         // [32][2][2] duplicated pairs (real only)
    float2* xinf2 = (float2*)xind;
    float2* p1f2 = (float2*)p1d;
    float2* p2f2 = (float2*)p2d;
    const ull* xinu = (const ull*)xind;
    const ull* p1du = (const ull*)p1d;
    const ull* p2du = (const ull*)p2d;
    const ull* w1u = (const ull*)sw1p;
    const ull* b1u = (const ull*)sb1p;
    const ull* w2u = (const ull*)sw2p;
    const ull* w3u = (const ull*)sw3p;

    const int* fb = frame + (size_t)sf * 147;

    // zero xind + p1d as pairs (p2d is fully written by conv2)
    for (int i = lane; i < 846; i += 32) ((float2*)wbase)[i] = make_float2(0.f, 0.f);
    __syncwarp();
    for (int i = lane; i < 147; i += 32) {
        int y = i / 21, r = i % 21, x = r / 3, c = r % 3;
        float v = (float)fb[i];
        xinf2[c * 90 + (y + 1) * 10 + (x + 1)] = make_float2(v, v);
    }
    // dir/pos via ballot (first row-major position where ch0 == 10)
    {
        int v0 = fb[lane * 3];
        unsigned m0 = __ballot_sync(0xffffffffu, v0 == 10);
        int p2i = 32 + lane;
        int v1 = (p2i < 49) ? fb[p2i * 3] : 0;
        unsigned m1 = __ballot_sync(0xffffffffu, (p2i < 49) && (v1 == 10));
        if (lane == 0) {
            int idx = m0 ? (__ffs(m0) - 1) : (m1 ? (31 + __ffs(m1)) : -1);
            int d = 0; float py = 0.5f, px = 0.5f;
            if (idx >= 0) {
                d = fb[idx * 3 + 2] & 3;
                py = (float)(idx / 7) * (1.f / 6.f);
                px = (float)(idx % 7) * (1.f / 6.f);
            }
            g_dir[sf] = d;
            g_pos[sf * 2 + 0] = py;
            g_pos[sf * 2 + 1] = px;
        }
    }
    __syncwarp();

    // -------- conv1 (3->16, k2 pad1, out 8x8) + relu + pool2 -> p1d interior [16][4][4]
    // lane = (cp in 0..7, quad in 0..3); channel pair (cp, cp+8), quadrant of 4x4 conv outputs
    {
        int cp = lane & 7, quad = lane >> 3;
        int qy = quad >> 1, qx = quad & 1;
        ull w[12];
        #pragma unroll
        for (int r2 = 0; r2 < 6; r2++) {
            ulonglong2 t = ld2(w1u + cp * 12 + r2 * 2);
            w[r2 * 2] = t.x; w[r2 * 2 + 1] = t.y;
        }
        float blo, bhi;
        { ull bp = b1u[cp]; unpk(bp, blo, bhi); }
        ull acc[16];
        #pragma unroll
        for (int i = 0; i < 16; i++) acc[i] = 0ULL;
        #pragma unroll
        for (int ic = 0; ic < 3; ic++) {
            const ull* xb = xinu + ic * 90 + (4 * qy) * 10 + 4 * qx;   // even offset
            ull in[5][5];
            #pragma unroll
            for (int r = 0; r < 5; r++) {
                ulonglong2 t0 = ld2(xb + r * 10);
                ulonglong2 t1 = ld2(xb + r * 10 + 2);
                in[r][0] = t0.x; in[r][1] = t0.y;
                in[r][2] = t1.x; in[r][3] = t1.y;
                in[r][4] = xb[r * 10 + 4];
            }
            ull w0 = w[ic * 4 + 0], w1 = w[ic * 4 + 1];
            ull w2 = w[ic * 4 + 2], w3 = w[ic * 4 + 3];
            #pragma unroll
            for (int oy = 0; oy < 4; oy++)
                #pragma unroll
                for (int ox = 0; ox < 4; ox++) {
                    ull* a = &acc[oy * 4 + ox];
                    fma2(*a, w0, in[oy][ox]);
                    fma2(*a, w1, in[oy][ox + 1]);
                    fma2(*a, w2, in[oy + 1][ox]);
                    fma2(*a, w3, in[oy + 1][ox + 1]);
                }
        }
        #pragma unroll
        for (int pr = 0; pr < 2; pr++)
            #pragma unroll
            for (int pc = 0; pc < 2; pc++) {
                float l0, h0, l1, h1, l2, h2, l3, h3;
                unpk(acc[(2 * pr) * 4 + 2 * pc],         l0, h0);
                unpk(acc[(2 * pr) * 4 + 2 * pc + 1],     l1, h1);
                unpk(acc[(2 * pr + 1) * 4 + 2 * pc],     l2, h2);
                unpk(acc[(2 * pr + 1) * 4 + 2 * pc + 1], l3, h3);
                float mlo = fmaxf(fmaxf(l0, l1), fmaxf(l2, l3));
                float mhi = fmaxf(fmaxf(h0, h1), fmaxf(h2, h3));
                float vlo = fmaxf(mlo + blo, 0.f);
                float vhi = fmaxf(mhi + bhi, 0.f);
                int py = 2 * qy + pr, px = 2 * qx + pc;
                p1f2[cp * 36 + (py + 1) * 6 + (px + 1)]       = make_float2(vlo, vlo);
                p1f2[(cp + 8) * 36 + (py + 1) * 6 + (px + 1)] = make_float2(vhi, vhi);
            }
    }
    __syncwarp();

    // -------- conv2 (16->32) + relu + pool -> p2d [32][2][2] (real only)
    // lane = (c in 0..15, h in 0..1); channel pair (c, c+16), conv-output rows {2h, 2h+1}
    {
        int c = lane & 15, h = lane >> 4;
        ull acc[8];
        #pragma unroll
        for (int i = 0; i < 8; i++) acc[i] = 0ULL;
        #pragma unroll 4
        for (int ic = 0; ic < 16; ic++) {
            ull in[3][5];
            #pragma unroll
            for (int r = 0; r < 3; r++) {
                const ull* rb = p1du + ic * 36 + (2 * h + r) * 6;   // even offset
                ulonglong2 t0 = ld2(rb);
                ulonglong2 t1 = ld2(rb + 2);
                in[r][0] = t0.x; in[r][1] = t0.y;
                in[r][2] = t1.x; in[r][3] = t1.y;
                in[r][4] = rb[4];
            }
            const ull* wb = w2u + (ic * 16 + c) * 4;                // even offset
            ulonglong2 wt0 = ld2(wb);
            ulonglong2 wt1 = ld2(wb + 2);
            ull wa = wt0.x, wbp = wt0.y, wc = wt1.x, wd = wt1.y;
            #pragma unroll
            for (int ry = 0; ry < 2; ry++)
                #pragma unroll
                for (int ox = 0; ox < 4; ox++) {
                    ull* a = &acc[ry * 4 + ox];
                    fma2(*a, wa,  in[ry][ox]);
                    fma2(*a, wbp, in[ry][ox + 1]);
                    fma2(*a, wc,  in[ry + 1][ox]);
                    fma2(*a, wd,  in[ry + 1][ox + 1]);
                }
        }
        ull bp = ((const ull*)sb2p)[c];
        float blo, bhi; unpk(bp, blo, bhi);
        #pragma unroll
        for (int px = 0; px < 2; px++) {
            float l0, h0, l1, h1, l2, h2, l3, h3;
            unpk(acc[0 * 4 + 2 * px],     l0, h0);
            unpk(acc[0 * 4 + 2 * px + 1], l1, h1);
            unpk(acc[1 * 4 + 2 * px],     l2, h2);
            unpk(acc[1 * 4 + 2 * px + 1], l3, h3);
            float mlo = fmaxf(fmaxf(l0, l1), fmaxf(l2, l3));
            float mhi = fmaxf(fmaxf(h0, h1), fmaxf(h2, h3));
            float vlo = fmaxf(mlo + blo, 0.f);
            float vhi = fmaxf(mhi + bhi, 0.f);
            p2f2[c * 4 + h * 2 + px]        = make_float2(vlo, vlo);
            p2f2[(c + 16) * 4 + h * 2 + px] = make_float2(vhi, vhi);
        }
    }
    __syncwarp();

    // -------- conv3 (32->64, out 3x3) + relu -> feats; SCATTER from 4 real pixels.
    // feats stored POSITION-MAJOR: g_feats[sf][p*64 + ch] — coalesced stores.
    {
        ull a[9];
        #pragma unroll
        for (int i = 0; i < 9; i++) a[i] = 0ULL;
        #pragma unroll 4
        for (int ic = 0; ic < 32; ic++) {
            ulonglong2 v01 = ld2(p2du + ic * 4);
            ulonglong2 v23 = ld2(p2du + ic * 4 + 2);
            ull v00 = v01.x, v0b = v01.y, v10 = v23.x, v11 = v23.y;
            const ull* wb = w3u + (ic * 32 + lane) * 4;             // even offset
            ulonglong2 wt0 = ld2(wb);
            ulonglong2 wt1 = ld2(wb + 2);
            ull w00 = wt0.x, w01 = wt0.y, w10 = wt1.x, w11 = wt1.y;
            fma2(a[0], w11, v00); fma2(a[1], w10, v00);
            fma2(a[3], w01, v00); fma2(a[4], w00, v00);
            fma2(a[1], w11, v0b); fma2(a[2], w10, v0b);
            fma2(a[4], w01, v0b); fma2(a[5], w00, v0b);
            fma2(a[3], w11, v10); fma2(a[4], w10, v10);
            fma2(a[6], w01, v10); fma2(a[7], w00, v10);
            fma2(a[4], w11, v11); fma2(a[5], w10, v11);
            fma2(a[7], w01, v11); fma2(a[8], w00, v11);
        }
        float* fbase = g_feats + (size_t)sf * FEAT_K;
        float b0 = sb3[lane], b1v = sb3[lane + 32];
        #pragma unroll
        for (int p = 0; p < 9; p++) {
            float lo, hi; unpk(a[p], lo, hi);
            fbase[p * 64 + lane]      = fmaxf(lo + b0, 0.f);
            fbase[p * 64 + 32 + lane] = fmaxf(hi + b1v, 0.f);
        }
        if (lane == 0) {
            fbase[576] = (float)ccol[sf];
            fbase[577] = (float)cobj[sf];
        }
        if (lane < 30) fbase[578 + lane] = 0.f;
    }
}

// ---------------- kernel: proj GEMM  emb[2B,64] = relu(feats * Wt + b), packed ----------------
// block: 256 m x 64 n, 256 threads, thread tile 8m x 8n (4 n-pairs); k-step 32, coalesced A staging
__global__ void __launch_bounds__(256) proj_kernel(const float* __restrict__ projb)
{
    __shared__ float As[32][260];      // [k][m]; row = 1040B
    __shared__ ull   Bsu[32 * 32];     // [k][slot]; slot(np) = (np&3)*8 + (np>>2)
    int tid = threadIdx.x;
    int m0 = blockIdx.x * 256;
    int tx = tid & 7, ty = tid >> 3;   // tx: n-group (8n), ty: 0..31 (8m)
    ull acc[8][4];
    #pragma unroll
    for (int i = 0; i < 8; i++)
        #pragma unroll
        for (int j = 0; j < 4; j++) acc[i][j] = 0ULL;

    for (int k0 = 0; k0 < FEAT_K; k0 += 32) {
        {   // stage A coalesced: 8 threads cover one row's 128B segment; 8 reps cover 256 rows
            int q = tid & 7, rbase = tid >> 3;
            #pragma unroll
            for (int rep = 0; rep < 8; rep++) {
                int row = rep * 32 + rbase;
                float4 v = *reinterpret_cast<const float4*>(
                    g_feats + (size_t)(m0 + row) * FEAT_K + k0 + q * 4);
                As[q * 4 + 0][row] = v.x; As[q * 4 + 1][row] = v.y;
                As[q * 4 + 2][row] = v.z; As[q * 4 + 3][row] = v.w;
            }
        }
        {   // stage B with conflict-free slot remap: 32 k x 64 n = 512 float4, 2 per thread
            #pragma unroll
            for (int rep = 0; rep < 2; rep++) {
                int idx = rep * 256 + tid;
                int k = idx >> 4, q = idx & 15;
                float4 bv = *reinterpret_cast<const float4*>(g_projwt + (k0 + k) * 64 + q * 4);
                int np0 = 2 * q, np1 = 2 * q + 1;
                int s0 = (np0 & 3) * 8 + (np0 >> 2);
                int s1 = (np1 & 3) * 8 + (np1 >> 2);
                float2* bf2 = (float2*)Bsu;
                bf2[k * 32 + s0] = make_float2(bv.x, bv.y);
                bf2[k * 32 + s1] = make_float2(bv.z, bv.w);
            }
        }
        __syncthreads();
        #pragma unroll
        for (int k = 0; k < 32; k++) {
            ull bp[4];
            #pragma unroll
            for (int j = 0; j < 4; j++) bp[j] = Bsu[k * 32 + j * 8 + tx];   // np = tx*4+j
            float4 alo = *reinterpret_cast<const float4*>(&As[k][ty * 8]);
            float4 ahi = *reinterpret_cast<const float4*>(&As[k][ty * 8 + 4]);
            float a[8] = {alo.x, alo.y, alo.z, alo.w, ahi.x, ahi.y, ahi.z, ahi.w};
            #pragma unroll
            for (int i = 0; i < 8; i++) {
                ull ad = pk_dup(a[i]);
                #pragma unroll
                for (int j = 0; j < 4; j++) fma2(acc[i][j], ad, bp[j]);
            }
        }
        __syncthreads();
    }
    #pragma unroll
    for (int i = 0; i < 8; i++) {
        int m = m0 + ty * 8 + i;
        #pragma unroll
        for (int j = 0; j < 4; j++) {
            int n = tx * 8 + 2 * j;
            float lo, hi; unpk(acc[i][j], lo, hi);
            g_emb[(size_t)m * 64 + n]     = fmaxf(lo + projb[n], 0.f);
            g_emb[(size_t)m * 64 + n + 1] = fmaxf(hi + projb[n + 1], 0.f);
        }
    }
}

// ---------------- kernel: fused comb + MLP (h1 -> LN -> relu -> h2 -> relu -> h3), packed ----------------
// smem floats: As[136*129] (comb -> Hs -> h2T overlay) + Bs[68*128] (half-K weight staging) + sh3[128*8]
#define MLP_AS (136 * 129)
#define MLP_BS (68 * 128)
#define MLP_SH3 (128 * 8)
#define MLP_SMEM_FLOATS (MLP_AS + MLP_BS + MLP_SH3)

__global__ void __launch_bounds__(256, 2) mlp_kernel(
    const float* __restrict__ h1b, const float* __restrict__ lng, const float* __restrict__ lnb,
    const float* __restrict__ h2b, const float* __restrict__ h3w, const float* __restrict__ h3b,
    float* __restrict__ out)
{
    extern __shared__ float smem[];
    float* As   = smem;                 // comb^T [k][m] stride 129; later Hs, later h2^T
    float* Bsf  = As + MLP_AS;          // weight staging [k-half][slot]
    float* sh3f = Bsf + MLP_BS;         // h3 transposed [k][8] (j<7 real)
    ull* Bsu  = (ull*)Bsf;
    ull* sh3u = (ull*)sh3f;

    int tid = threadIdx.x;
    int m0 = blockIdx.x * 128;
    int tx = tid & 15, ty = tid >> 4;

    auto load_bs_half = [&](const float* wsrc, int rows) {
        for (int i = tid; i < rows * 32; i += 256) {
            int k = i >> 5, q = i & 31;
            float4 bv = *reinterpret_cast<const float4*>(wsrc + k * 128 + q * 4);
            int np0 = 2 * q, np1 = 2 * q + 1;
            int s0 = (np0 & 3) * 16 + (np0 >> 2);
            int s1 = (np1 & 3) * 16 + (np1 >> 2);
            float2* bf2 = (float2*)Bsu;
            bf2[k * 64 + s0] = make_float2(bv.x, bv.y);
            bf2[k * 64 + s1] = make_float2(bv.z, bv.w);
        }
    };

    // ---- build comb directly into As; stage sh3; stage h1 weights half 0
    for (int i = tid; i < 128 * COMB_K; i += 256) {
        int m = i / COMB_K, k = i - m * COMB_K;
        int b = m0 + m;
        float v;
        if (k < 64)       v = g_emb[(size_t)b * 64 + k];
        else if (k < 128) v = g_emb[(size_t)(NB + b) * 64 + (k - 64)];
        else if (k < 130) {
            int delta = ((g_dir[NB + b] - g_dir[b]) + 4) & 3;
            float ang = (float)delta * (2.0f * 3.14159f / 4.0f);
            v = (k == 128) ? sinf(ang) : cosf(ang);
        }
        else if (k == 130) v = g_pos[(NB + b) * 2 + 0] - g_pos[b * 2 + 0];
        else if (k == 131) v = g_pos[(NB + b) * 2 + 1] - g_pos[b * 2 + 1];
        else v = 0.f;
        As[k * 129 + m] = v;
    }
    for (int i = tid; i < 128 * 8; i += 256) {
        int k = i >> 3, j = i & 7;
        sh3f[i] = (j < 7) ? h3w[j * 128 + k] : 0.f;
    }
    load_bs_half(g_h1wt, 68);
    __syncthreads();

    // ---- GEMM1: h[128m][128n] = comb * h1wt  (half-K staged, k unrolled x2)
    ull acc[8][4];
    #pragma unroll
    for (int i = 0; i < 8; i++)
        #pragma unroll
        for (int j = 0; j < 4; j++) acc[i][j] = 0ULL;
    #pragma unroll 1
    for (int half = 0; half < 2; half++) {
        if (half) {
            __syncthreads();
            load_bs_half(g_h1wt + 68 * 128, 68);
            __syncthreads();
        }
        int kb = half * 68;
        for (int k = 0; k < 68; k += 2) {
            ull bp0[4], bp1[4];
            float a0[8], a1[8];
            #pragma unroll
            for (int j = 0; j < 4; j++) {
                bp0[j] = Bsu[k * 64 + j * 16 + tx];
                bp1[j] = Bsu[(k + 1) * 64 + j * 16 + tx];
            }
            #pragma unroll
            for (int i = 0; i < 8; i++) {
                a0[i] = As[(kb + k) * 129 + ty * 8 + i];
                a1[i] = As[(kb + k + 1) * 129 + ty * 8 + i];
            }
            #pragma unroll
            for (int i = 0; i < 8; i++) {
                ull ad = pk_dup(a0[i]);
                #pragma unroll
                for (int j = 0; j < 4; j++) fma2(acc[i][j], ad, bp0[j]);
            }
            #pragma unroll
            for (int i = 0; i < 8; i++) {
                ull ad = pk_dup(a1[i]);
                #pragma unroll
                for (int j = 0; j < 4; j++) fma2(acc[i][j], ad, bp1[j]);
            }
        }
    }
    __syncthreads();   // all reads of As (comb) done

    // ---- write pre-LN h (+bias) transposed into As region (Hs[feature][m]); stage h2 half 0
    float* Hs = As;
    #pragma unroll
    for (int j = 0; j < 4; j++) {
        int n = tx * 8 + 2 * j;
        float bn0 = h1b[n], bn1 = h1b[n + 1];
        #pragma unroll
        for (int i = 0; i < 8; i++) {
            int m = ty * 8 + i;
            float lo, hi; unpk(acc[i][j], lo, hi);
            Hs[n * 129 + m]       = lo + bn0;
            Hs[(n + 1) * 129 + m] = hi + bn1;
        }
    }
    load_bs_half(g_h2wt, 64);
    __syncthreads();

    // ---- LayerNorm + relu: 2 threads per sample row
    {
        int m = tid >> 1, halfr = tid & 1;
        int kb = halfr * 64;
        float s = 0.f, s2 = 0.f;
        for (int k = kb; k < kb + 64; k++) {
            float v = Hs[k * 129 + m];
            s += v; s2 += v * v;
        }
        s  += __shfl_xor_sync(0xffffffffu, s, 1);
        s2 += __shfl_xor_sync(0xffffffffu, s2, 1);
        float mu = s * (1.f / 128.f);
        float var = s2 * (1.f / 128.f) - mu * mu;
        float rs = rsqrtf(var + 1e-5f);
        for (int k = kb; k < kb + 64; k++) {
            float v = Hs[k * 129 + m];
            Hs[k * 129 + m] = fmaxf((v - mu) * rs * lng[k] + lnb[k], 0.f);
        }
    }
    __syncthreads();

    // ---- GEMM2: h2 = relu(h * h2wt + b)  (half-K staged, k unrolled x2)
    ull acc2[8][4];
    #pragma unroll
    for (int i = 0; i < 8; i++)
        #pragma unroll
        for (int j = 0; j < 4; j++) acc2[i][j] = 0ULL;
    #pragma unroll 1
    for (int half = 0; half < 2; half++) {
        if (half) {
            __syncthreads();
            load_bs_half(g_h2wt + 64 * 128, 64);
            __syncthreads();
        }
        int kb = half * 64;
        for (int k = 0; k < 64; k += 2) {
            ull bp0[4], bp1[4];
            float a0[8], a1[8];
            #pragma unroll
            for (int j = 0; j < 4; j++) {
                bp0[j] = Bsu[k * 64 + j * 16 + tx];
                bp1[j] = Bsu[(k + 1) * 64 + j * 16 + tx];
            }
            #pragma unroll
            for (int i = 0; i < 8; i++) {
                a0[i] = Hs[(kb + k) * 129 + ty * 8 + i];
                a1[i] = Hs[(kb + k + 1) * 129 + ty * 8 + i];
            }
            #pragma unroll
            for (int i = 0; i < 8; i++) {
                ull ad = pk_dup(a0[i]);
                #pragma unroll
                for (int j = 0; j < 4; j++) fma2(acc2[i][j], ad, bp0[j]);
            }
            #pragma unroll
            for (int i = 0; i < 8; i++) {
                ull ad = pk_dup(a1[i]);
                #pragma unroll
                for (int j = 0; j < 4; j++) fma2(acc2[i][j], ad, bp1[j]);
            }
        }
    }
    __syncthreads();   // all reads of Hs done

    // ---- write h2 (relu) transposed into As region again
    #pragma unroll
    for (int j = 0; j < 4; j++) {
        int n = tx * 8 + 2 * j;
        float bn0 = h2b[n], bn1 = h2b[n + 1];
        #pragma unroll
        for (int i = 0; i < 8; i++) {
            int m = ty * 8 + i;
            float lo, hi; unpk(acc2[i][j], lo, hi);
            As[n * 129 + m]       = fmaxf(lo + bn0, 0.f);
            As[(n + 1) * 129 + m] = fmaxf(hi + bn1, 0.f);
        }
    }
    __syncthreads();

    // ---- h3: out[m][7]  (packed j-pairs via transposed sh3)
    if (tid < 128) {
        int m = tid;
        ull acc3[4];
        #pragma unroll
        for (int j = 0; j < 4; j++) acc3[j] = 0ULL;
        for (int k = 0; k < 128; k++) {
            ull ad = pk_dup(As[k * 129 + m]);
            #pragma unroll
            for (int j = 0; j < 4; j++) fma2(acc3[j], ad, sh3u[k * 4 + j]);
        }
        float r[8];
        #pragma unroll
        for (int j = 0; j < 4; j++) unpk(acc3[j], r[2 * j], r[2 * j + 1]);
        #pragma unroll
        for (int j = 0; j < 7; j++)
            out[(size_t)(m0 + m) * 7 + j] = r[j] + h3b[j];
    }
}

// ---------------- launch ----------------
extern "C" void kernel_launch(void* const* d_in, const int* in_sizes, int n_in,
                              void* d_out, int out_size)
{
    const int*   frame = (const int*)d_in[0];
    const int*   ccol  = (const int*)d_in[1];
    const int*   cobj  = (const int*)d_in[2];
    const float* c1w = (const float*)d_in[3];
    const float* c1b = (const float*)d_in[4];
    const float* c2w = (const float*)d_in[5];
    const float* c2b = (const float*)d_in[6];
    const float* c3w = (const float*)d_in[7];
    const float* c3b = (const float*)d_in[8];
    const float* pw  = (const float*)d_in[9];
    const float* pb  = (const float*)d_in[10];
    const float* h1w = (const float*)d_in[11];
    const float* h1b = (const float*)d_in[12];
    const float* lng = (const float*)d_in[13];
    const float* lnb = (const float*)d_in[14];
    const float* h2w = (const float*)d_in[15];
    const float* h2b = (const float*)d_in[16];
    const float* h3w = (const float*)d_in[17];
    const float* h3b = (const float*)d_in[18];
    float* out = (float*)d_out;

    cudaFuncSetAttribute(encode_kernel, cudaFuncAttributeMaxDynamicSharedMemorySize,
                         ENC_SMEM_FLOATS * (int)sizeof(float));
    cudaFuncSetAttribute(mlp_kernel, cudaFuncAttributeMaxDynamicSharedMemorySize,
                         MLP_SMEM_FLOATS * (int)sizeof(float));

    {
        int total = FEAT_K * 64 + COMB_K * 128 + 128 * 128;
        prep_kernel<<<(total + 255) / 256, 256>>>(pw, h1w, h2w);
    }
    encode_kernel<<<(NSF + ENC_WARPS - 1) / ENC_WARPS, ENC_THREADS,
                    ENC_SMEM_FLOATS * sizeof(float)>>>(
        frame, ccol, cobj, c1w, c1b, c2w, c2b, c3w, c3b);
    proj_kernel<<<NSF / 256, 256>>>(pb);
    mlp_kernel<<<NB / 128, 256, MLP_SMEM_FLOATS * sizeof(float)>>>(
        h1b, lng, lnb, h2b, h3w, h3b, out);
}